// round 3
// baseline (speedup 1.0000x reference)
#include <cuda_runtime.h>

#define Bn   256
#define Tn   512
#define Dn   64
#define En   128
#define H1n  128
#define H2n  64
#define Vn   10000
#define ML   30
#define SOS_ 1
#define EOS_ 2

// ---------------- persistent decoder state (device globals, no allocs) --------
__device__ float g_h1[2][Bn * H1n];   // ping-pong (multiple blocks read while writing)
__device__ float g_c1[Bn * H1n];
__device__ float g_h2[Bn * H2n];
__device__ float g_c2[Bn * H2n];
__device__ float g_ctx[Bn * Dn];
__device__ float g_x[Bn * (H2n + Dn)];          // [h2 | ctx] input to pred GEMM
__device__ unsigned long long g_amax[Bn];       // packed (fkey(val)<<32 | ~v)

__device__ __forceinline__ unsigned int fkey(float f) {
    unsigned int u = __float_as_uint(f);
    return (u & 0x80000000u) ? ~u : (u | 0x80000000u);   // monotonic float->uint
}
__device__ __forceinline__ float sigm(float x) { return 1.0f / (1.0f + expf(-x)); }

// ---------------- init: zero state, tok = SOS -------------------------------
__global__ void k_init() {
    int i = blockIdx.x * blockDim.x + threadIdx.x;
    if (i < Bn * H1n) { g_h1[0][i] = 0.f; g_c1[i] = 0.f; }
    if (i < Bn * H2n) { g_h2[i] = 0.f; g_c2[i] = 0.f; }
    if (i < Bn * Dn)  { g_ctx[i] = 0.f; }
    if (i < Bn)       { g_amax[i] = (unsigned long long)(~(unsigned int)SOS_); } // decodes to tok=1
}

// ---------------- LSTM1: embed(argmax) + gates GEMM + cell update -----------
// grid (8 k-tiles of 16, 16 b-tiles of 16), 256 threads
__global__ void k_lstm1(const float* __restrict__ wih, const float* __restrict__ whh,
                        const float* __restrict__ bih, const float* __restrict__ bhh,
                        const float* __restrict__ emb, int ph) {
    __shared__ float s_in[192][16];   // [k][b]  (embed|ctx)
    __shared__ float s_h[128][16];    // [k][b]  h1
    __shared__ float s_g[16][64];     // [b][gate*16+kk]
    __shared__ int   s_tok[16];
    const float* __restrict__ h1in = g_h1[ph];
    float* __restrict__ h1out = g_h1[ph ^ 1];

    int kt = blockIdx.x, bt = blockIdx.y;
    int b0 = bt * 16;
    int tid = threadIdx.x;

    if (tid < 16) {
        unsigned long long a = g_amax[b0 + tid];
        s_tok[tid] = (int)(~(unsigned int)(a & 0xFFFFFFFFull));
    }
    __syncthreads();

    for (int idx = tid; idx < 16 * 192; idx += 256) {
        int bb = idx / 192, k = idx - bb * 192;
        float v;
        if (k < En) {
            int tok = s_tok[bb];
            v = (tok == EOS_) ? 0.f : emb[(size_t)tok * En + k];   // padding row zeroed
        } else {
            v = g_ctx[(b0 + bb) * Dn + (k - En)];
        }
        s_in[k][bb] = v;
    }
    for (int idx = tid; idx < 16 * 128; idx += 256) {
        int bb = idx >> 7, k = idx & 127;
        s_h[k][bb] = h1in[(b0 + bb) * H1n + k];
    }
    __syncthreads();

    int col = tid & 63;            // gate*16 + kk
    int bg  = tid >> 6;            // 4 b's per thread
    int gate = col >> 4, kk = col & 15;
    int j = gate * H1n + kt * 16 + kk;

    float acc[4] = {0.f, 0.f, 0.f, 0.f};
    const float4* wr = (const float4*)(wih + (size_t)j * 192);
    #pragma unroll 8
    for (int k4 = 0; k4 < 48; k4++) {
        float4 w = wr[k4];
        int k = k4 * 4;
        float4 x0 = *(const float4*)(&s_in[k + 0][bg * 4]);
        float4 x1 = *(const float4*)(&s_in[k + 1][bg * 4]);
        float4 x2 = *(const float4*)(&s_in[k + 2][bg * 4]);
        float4 x3 = *(const float4*)(&s_in[k + 3][bg * 4]);
        acc[0] += w.x*x0.x + w.y*x1.x + w.z*x2.x + w.w*x3.x;
        acc[1] += w.x*x0.y + w.y*x1.y + w.z*x2.y + w.w*x3.y;
        acc[2] += w.x*x0.z + w.y*x1.z + w.z*x2.z + w.w*x3.z;
        acc[3] += w.x*x0.w + w.y*x1.w + w.z*x2.w + w.w*x3.w;
    }
    const float4* wr2 = (const float4*)(whh + (size_t)j * 128);
    #pragma unroll 8
    for (int k4 = 0; k4 < 32; k4++) {
        float4 w = wr2[k4];
        int k = k4 * 4;
        float4 x0 = *(const float4*)(&s_h[k + 0][bg * 4]);
        float4 x1 = *(const float4*)(&s_h[k + 1][bg * 4]);
        float4 x2 = *(const float4*)(&s_h[k + 2][bg * 4]);
        float4 x3 = *(const float4*)(&s_h[k + 3][bg * 4]);
        acc[0] += w.x*x0.x + w.y*x1.x + w.z*x2.x + w.w*x3.x;
        acc[1] += w.x*x0.y + w.y*x1.y + w.z*x2.y + w.w*x3.y;
        acc[2] += w.x*x0.z + w.y*x1.z + w.z*x2.z + w.w*x3.z;
        acc[3] += w.x*x0.w + w.y*x1.w + w.z*x2.w + w.w*x3.w;
    }
    float bias = bih[j] + bhh[j];
    s_g[bg * 4 + 0][col] = acc[0] + bias;
    s_g[bg * 4 + 1][col] = acc[1] + bias;
    s_g[bg * 4 + 2][col] = acc[2] + bias;
    s_g[bg * 4 + 3][col] = acc[3] + bias;
    __syncthreads();

    {   // cell update: 16b x 16k
        int bb = tid >> 4, k2 = tid & 15;
        float gi = s_g[bb][ 0 + k2], gf = s_g[bb][16 + k2];
        float gg = s_g[bb][32 + k2], go = s_g[bb][48 + k2];
        int idx = (b0 + bb) * H1n + kt * 16 + k2;
        float c = sigm(gf) * g_c1[idx] + sigm(gi) * tanhf(gg);
        g_c1[idx] = c;
        h1out[idx] = sigm(go) * tanhf(c);
    }
}

// ---------------- LSTM2: gates + cell, writes h2 into g_h2 and g_x ----------
// grid 32 (b-tiles of 8), 256 threads (one per gate column)
__global__ void k_lstm2(const float* __restrict__ wih, const float* __restrict__ whh,
                        const float* __restrict__ bih, const float* __restrict__ bhh,
                        int ph) {
    __shared__ float s_c[192][8];     // [k][b]  (h1_new | h2_old)
    __shared__ float s_g[8][256];
    const float* __restrict__ h1new = g_h1[ph ^ 1];
    int b0 = blockIdx.x * 8;
    int tid = threadIdx.x;

    for (int idx = tid; idx < 8 * 192; idx += 256) {
        int bb = idx / 192, k = idx - bb * 192;
        float v = (k < H1n) ? h1new[(b0 + bb) * H1n + k]
                            : g_h2[(b0 + bb) * H2n + (k - H1n)];
        s_c[k][bb] = v;
    }
    __syncthreads();

    int j = tid;
    float acc[8] = {0,0,0,0,0,0,0,0};
    const float4* wr = (const float4*)(wih + (size_t)j * 128);
    #pragma unroll 4
    for (int k4 = 0; k4 < 32; k4++) {
        float4 w = wr[k4];
        float wl[4] = {w.x, w.y, w.z, w.w};
        #pragma unroll
        for (int kk = 0; kk < 4; kk++) {
            int k = k4 * 4 + kk;
            float4 xa = *(const float4*)(&s_c[k][0]);
            float4 xb = *(const float4*)(&s_c[k][4]);
            acc[0] += wl[kk]*xa.x; acc[1] += wl[kk]*xa.y;
            acc[2] += wl[kk]*xa.z; acc[3] += wl[kk]*xa.w;
            acc[4] += wl[kk]*xb.x; acc[5] += wl[kk]*xb.y;
            acc[6] += wl[kk]*xb.z; acc[7] += wl[kk]*xb.w;
        }
    }
    const float4* wr2 = (const float4*)(whh + (size_t)j * 64);
    #pragma unroll 4
    for (int k4 = 0; k4 < 16; k4++) {
        float4 w = wr2[k4];
        float wl[4] = {w.x, w.y, w.z, w.w};
        #pragma unroll
        for (int kk = 0; kk < 4; kk++) {
            int k = 128 + k4 * 4 + kk;
            float4 xa = *(const float4*)(&s_c[k][0]);
            float4 xb = *(const float4*)(&s_c[k][4]);
            acc[0] += wl[kk]*xa.x; acc[1] += wl[kk]*xa.y;
            acc[2] += wl[kk]*xa.z; acc[3] += wl[kk]*xa.w;
            acc[4] += wl[kk]*xb.x; acc[5] += wl[kk]*xb.y;
            acc[6] += wl[kk]*xb.z; acc[7] += wl[kk]*xb.w;
        }
    }
    float bias = bih[j] + bhh[j];
    #pragma unroll
    for (int i = 0; i < 8; i++) s_g[i][j] = acc[i] + bias;
    __syncthreads();

    for (int idx = tid; idx < 8 * 64; idx += 256) {
        int bb = idx >> 6, k2 = idx & 63;
        float gi = s_g[bb][k2],        gf = s_g[bb][ 64 + k2];
        float gg = s_g[bb][128 + k2],  go = s_g[bb][192 + k2];
        int gidx = (b0 + bb) * H2n + k2;
        float c = sigm(gf) * g_c2[gidx] + sigm(gi) * tanhf(gg);
        g_c2[gidx] = c;
        float h = sigm(go) * tanhf(c);
        g_h2[gidx] = h;
        g_x[(b0 + bb) * (H2n + Dn) + k2] = h;
    }
}

// ---------------- attention: query + energy + masked softmax + context ------
// grid 256 (one block per batch row), 256 threads. Also zeroes g_amax[b].
__global__ void k_attn(const float* __restrict__ wq, const float* __restrict__ bq,
                       const float* __restrict__ enc_key, const float* __restrict__ enc_val,
                       const int* __restrict__ mask) {
    __shared__ float s_q[64], s_h2[64], s_e[512], s_w[512], s_red[64], s_p[256];
    int b = blockIdx.x, tid = threadIdx.x;
    if (tid == 0) g_amax[b] = 0ull;
    if (tid < 64) s_h2[tid] = g_h2[b * H2n + tid];
    __syncthreads();
    if (tid < 64) {
        float a = bq[tid];
        const float* w = wq + tid * H2n;
        #pragma unroll
        for (int k = 0; k < 64; k++) a += w[k] * s_h2[k];
        s_q[tid] = a;
    }
    __syncthreads();

    int warp = tid >> 5, lane = tid & 31;
    float q0 = s_q[2 * lane], q1 = s_q[2 * lane + 1];
    #pragma unroll 4
    for (int it = 0; it < 64; it++) {
        int t = it * 8 + warp;
        float2 kv = *(const float2*)(enc_key + (size_t)t * Bn * Dn + b * Dn + 2 * lane);
        float p = q0 * kv.x + q1 * kv.y;
        p += __shfl_down_sync(0xffffffffu, p, 16);
        p += __shfl_down_sync(0xffffffffu, p, 8);
        p += __shfl_down_sync(0xffffffffu, p, 4);
        p += __shfl_down_sync(0xffffffffu, p, 2);
        p += __shfl_down_sync(0xffffffffu, p, 1);
        if (lane == 0) s_e[t] = p;
    }
    __syncthreads();

    float m = fmaxf(s_e[tid], s_e[tid + 256]);
    for (int o = 16; o; o >>= 1) m = fmaxf(m, __shfl_down_sync(0xffffffffu, m, o));
    if (lane == 0) s_red[warp] = m;
    __syncthreads();
    if (tid == 0) {
        float mm = s_red[0];
        for (int i = 1; i < 8; i++) mm = fmaxf(mm, s_red[i]);
        s_red[32] = mm;
    }
    __syncthreads();
    float mx = s_red[32];
    float e0 = expf(s_e[tid] - mx), e1 = expf(s_e[tid + 256] - mx);
    int m0 = mask[b * Tn + tid], m1 = mask[b * Tn + tid + 256];
    float s  = e0 + e1;
    float ws = (m0 ? e0 : 0.f) + (m1 ? e1 : 0.f);
    for (int o = 16; o; o >>= 1) {
        s  += __shfl_down_sync(0xffffffffu, s,  o);
        ws += __shfl_down_sync(0xffffffffu, ws, o);
    }
    if (lane == 0) { s_red[warp] = s; s_red[8 + warp] = ws; }
    __syncthreads();
    if (tid == 0) {
        float S = 0.f, WS = 0.f;
        for (int i = 0; i < 8; i++) { S += s_red[i]; WS += s_red[8 + i]; }
        s_red[33] = 1.0f / (S * fmaxf(WS / S, 2e-30f));  // mask*e*inv == m_att/denom
    }
    __syncthreads();
    float inv = s_red[33];
    s_w[tid]       = m0 ? e0 * inv : 0.f;
    s_w[tid + 256] = m1 ? e1 * inv : 0.f;
    __syncthreads();

    int d = tid & 63, ch = tid >> 6;
    float a0 = 0.f, a1 = 0.f;
    const float* vb = enc_val + (size_t)b * Dn + d;
    #pragma unroll 4
    for (int t = ch * 128; t < ch * 128 + 128; t += 2) {
        a0 += s_w[t]     * vb[(size_t)t * (Bn * Dn)];
        a1 += s_w[t + 1] * vb[(size_t)(t + 1) * (Bn * Dn)];
    }
    s_p[ch * 64 + d] = a0 + a1;
    __syncthreads();
    if (tid < 64) {
        float c = s_p[tid] + s_p[64 + tid] + s_p[128 + tid] + s_p[192 + tid];
        g_ctx[b * Dn + tid] = c;
        g_x[b * (H2n + Dn) + H2n + tid] = c;
    }
}

// ---------------- pred GEMM: [h2|ctx] @ wp^T + bp, fused argmax -------------
// grid (157 v-tiles of 64, 4 b-tiles of 64), 256 threads, 4x4 register tiles
__global__ void k_pred(const float* __restrict__ wp, const float* __restrict__ bp,
                       float* __restrict__ out, int step) {
    __shared__ float s_x[128][68];   // [k][b], padded for LDS.128 alignment
    int vt = blockIdx.x, bt = blockIdx.y;
    int b0 = bt * 64;
    int tid = threadIdx.x;

    for (int idx = tid; idx < 64 * 128; idx += 256) {
        int bb = idx >> 7, k = idx & 127;
        s_x[k][bb] = g_x[(b0 + bb) * 128 + k];
    }
    __syncthreads();

    int vg = tid & 15, bg = tid >> 4;
    int v0 = vt * 64 + vg * 4;
    bool vok = (v0 + 3) < Vn;           // Vn % 4 == 0
    int vl = vok ? v0 : 0;
    const float4* w0 = (const float4*)(wp + (size_t)(vl + 0) * 128);
    const float4* w1 = (const float4*)(wp + (size_t)(vl + 1) * 128);
    const float4* w2 = (const float4*)(wp + (size_t)(vl + 2) * 128);
    const float4* w3 = (const float4*)(wp + (size_t)(vl + 3) * 128);
    int bb0 = bg * 4;

    float acc[4][4];
    #pragma unroll
    for (int i = 0; i < 4; i++)
        #pragma unroll
        for (int jj = 0; jj < 4; jj++) acc[i][jj] = 0.f;

    #pragma unroll 4
    for (int k4 = 0; k4 < 32; k4++) {
        float4 wa = w0[k4], wb = w1[k4], wc = w2[k4], wd = w3[k4];
        float wA[4] = {wa.x, wa.y, wa.z, wa.w};
        float wB[4] = {wb.x, wb.y, wb.z, wb.w};
        float wC[4] = {wc.x, wc.y, wc.z, wc.w};
        float wD[4] = {wd.x, wd.y, wd.z, wd.w};
        #pragma unroll
        for (int kk = 0; kk < 4; kk++) {
            int k = k4 * 4 + kk;
            float4 x = *(const float4*)(&s_x[k][bb0]);
            acc[0][0] += x.x * wA[kk]; acc[0][1] += x.x * wB[kk];
            acc[0][2] += x.x * wC[kk]; acc[0][3] += x.x * wD[kk];
            acc[1][0] += x.y * wA[kk]; acc[1][1] += x.y * wB[kk];
            acc[1][2] += x.y * wC[kk]; acc[1][3] += x.y * wD[kk];
            acc[2][0] += x.z * wA[kk]; acc[2][1] += x.z * wB[kk];
            acc[2][2] += x.z * wC[kk]; acc[2][3] += x.z * wD[kk];
            acc[3][0] += x.w * wA[kk]; acc[3][1] += x.w * wB[kk];
            acc[3][2] += x.w * wC[kk]; acc[3][3] += x.w * wD[kk];
        }
    }

    float b0v = vok ? bp[v0] : 0.f, b1v = vok ? bp[v0 + 1] : 0.f;
    float b2v = vok ? bp[v0 + 2] : 0.f, b3v = vok ? bp[v0 + 3] : 0.f;

    #pragma unroll
    for (int i = 0; i < 4; i++) {
        int bi = b0 + bb0 + i;
        float r0 = acc[i][0] + b0v, r1 = acc[i][1] + b1v;
        float r2 = acc[i][2] + b2v, r3 = acc[i][3] + b3v;
        if (vok) {
            *(float4*)(out + (size_t)bi * ML * Vn + (size_t)step * Vn + v0)
                = make_float4(r0, r1, r2, r3);
        }
        float best = r0; int bv = v0;
        if (r1 > best) { best = r1; bv = v0 + 1; }
        if (r2 > best) { best = r2; bv = v0 + 2; }
        if (r3 > best) { best = r3; bv = v0 + 3; }
        unsigned long long pk = vok
            ? ((unsigned long long)fkey(best) << 32) | (unsigned int)(~bv)
            : 0ull;
        #pragma unroll
        for (int o = 8; o; o >>= 1) {
            unsigned long long other = __shfl_down_sync(0xffffffffu, pk, o, 16);
            if (other > pk) pk = other;
        }
        if (vg == 0) atomicMax(&g_amax[bi], pk);
    }
}

// ---------------- host: graph-capturable launch sequence --------------------
extern "C" void kernel_launch(void* const* d_in, const int* in_sizes, int n_in,
                              void* d_out, int out_size) {
    const float* enc_key = (const float*)d_in[0];
    const float* enc_val = (const float*)d_in[1];
    const int*   mask    = (const int*)d_in[2];
    const float* emb     = (const float*)d_in[3];
    const float* w_ih1   = (const float*)d_in[4];
    const float* w_hh1   = (const float*)d_in[5];
    const float* b_ih1   = (const float*)d_in[6];
    const float* b_hh1   = (const float*)d_in[7];
    const float* w_ih2   = (const float*)d_in[8];
    const float* w_hh2   = (const float*)d_in[9];
    const float* b_ih2   = (const float*)d_in[10];
    const float* b_hh2   = (const float*)d_in[11];
    const float* wq      = (const float*)d_in[12];
    const float* bq      = (const float*)d_in[13];
    const float* wp      = (const float*)d_in[14];
    const float* bp      = (const float*)d_in[15];
    float* out = (float*)d_out;

    k_init<<<128, 256>>>();
    for (int s = 0; s < ML; s++) {
        int ph = s & 1;
        k_lstm1<<<dim3(8, 16), 256>>>(w_ih1, w_hh1, b_ih1, b_hh1, emb, ph);
        k_lstm2<<<32, 256>>>(w_ih2, w_hh2, b_ih2, b_hh2, ph);
        k_attn<<<256, 256>>>(wq, bq, enc_key, enc_val, mask);
        k_pred<<<dim3(157, 4), 256>>>(wp, bp, out, s);
    }
}

// round 4
// speedup vs baseline: 1.0600x; 1.0600x over previous
#include <cuda_runtime.h>

#define Bn   256
#define Tn   512
#define Dn   64
#define En   128
#define H1n  128
#define H2n  64
#define Vn   10000
#define ML   30
#define SOS_ 1
#define EOS_ 2

// ---------------- persistent decoder state (device globals, no allocs) ------
__device__ float g_h1[Bn * H1n];
__device__ float g_c1[Bn * H1n];
__device__ float g_h2[Bn * H2n];
__device__ float g_c2[Bn * H2n];
__device__ float g_q[Bn * Dn];
__device__ float g_x[Bn * 128];                 // [h2(64) | ctx(64)] pred input
__device__ unsigned long long g_amax[Bn];       // packed (fkey(val)<<32 | ~v)

__device__ __forceinline__ unsigned int fkey(float f) {
    unsigned int u = __float_as_uint(f);
    return (u & 0x80000000u) ? ~u : (u | 0x80000000u);
}
__device__ __forceinline__ float sigm(float x) { return 1.0f / (1.0f + expf(-x)); }

// packed fp32 pair FMA: d(lo,hi) += a(lo,hi)*b(lo,hi)
__device__ __forceinline__ void fma2(unsigned long long& d, unsigned long long a,
                                     unsigned long long b) {
    asm("fma.rn.f32x2 %0, %1, %2, %0;" : "+l"(d) : "l"(a), "l"(b));
}
__device__ __forceinline__ float hsum2(unsigned long long a) {
    unsigned int ul, uh;
    asm("mov.b64 {%0, %1}, %2;" : "=r"(ul), "=r"(uh) : "l"(a));
    return __uint_as_float(ul) + __uint_as_float(uh);
}

// ---------------- init ------------------------------------------------------
__global__ void k_init() {
    int i = blockIdx.x * blockDim.x + threadIdx.x;
    if (i < Bn * H1n) { g_h1[i] = 0.f; g_c1[i] = 0.f; }
    if (i < Bn * H2n) { g_h2[i] = 0.f; g_c2[i] = 0.f; }
    if (i < Bn * 128) g_x[i] = 0.f;
    if (i < Bn) g_amax[i] = (unsigned long long)(~(unsigned int)SOS_);
}

// ---------------- fused rnn: embed + lstm1 + lstm2 + query ------------------
// grid 64 (4 batch rows each), 256 threads
__global__ void __launch_bounds__(256) k_rnn(
    const float* __restrict__ wih1, const float* __restrict__ whh1,
    const float* __restrict__ bih1, const float* __restrict__ bhh1,
    const float* __restrict__ wih2, const float* __restrict__ whh2,
    const float* __restrict__ bih2, const float* __restrict__ bhh2,
    const float* __restrict__ wq,   const float* __restrict__ bq,
    const float* __restrict__ emb)
{
    __shared__ __align__(16) float s_x[4][192];    // [b][k] (emb|ctx)
    __shared__ __align__(16) float s_h1[4][128];   // h1 prev
    __shared__ __align__(16) float s_g1[4][512];
    __shared__ __align__(16) float s_h1n[4][128];
    __shared__ __align__(16) float s_h2[4][64];    // h2 prev
    __shared__ __align__(16) float s_g2[4][256];
    __shared__ __align__(16) float s_h2n[4][64];
    __shared__ int s_tok[4];

    const int tid = threadIdx.x;
    const int b0 = blockIdx.x * 4;

    if (tid < 4) {
        unsigned long long a = g_amax[b0 + tid];
        s_tok[tid] = (int)(~(unsigned int)(a & 0xFFFFFFFFull));
        g_amax[b0 + tid] = 0ull;          // reset for this step's pred
    }
    __syncthreads();

    for (int idx = tid; idx < 4 * 192; idx += 256) {
        int b = idx / 192, k = idx - b * 192;
        float v;
        if (k < En) {
            int tok = s_tok[b];
            v = (tok == EOS_) ? 0.f : emb[(size_t)tok * En + k];  // padding row
        } else {
            v = g_x[(b0 + b) * 128 + 64 + (k - En)];              // ctx
        }
        s_x[b][k] = v;
    }
    for (int idx = tid; idx < 512; idx += 256) {
        int b = idx >> 7, k = idx & 127;
        s_h1[b][k] = g_h1[(b0 + b) * H1n + k];
    }
    { int b = tid >> 6, k = tid & 63; s_h2[b][k] = g_h2[(b0 + b) * H2n + k]; }
    __syncthreads();

    // lstm1 gates: thread handles weight rows tid and tid+256, all 4 b
    {
        unsigned long long acc[2][4] = {};
        const int j0 = tid, j1 = tid + 256;
        const ulonglong2* w0 = (const ulonglong2*)(wih1 + (size_t)j0 * 192);
        const ulonglong2* w1 = (const ulonglong2*)(wih1 + (size_t)j1 * 192);
        #pragma unroll 4
        for (int k4 = 0; k4 < 48; k4++) {
            ulonglong2 wa = w0[k4], wb = w1[k4];
            #pragma unroll
            for (int b = 0; b < 4; b++) {
                ulonglong2 xv = *(const ulonglong2*)&s_x[b][k4 * 4];
                fma2(acc[0][b], wa.x, xv.x); fma2(acc[0][b], wa.y, xv.y);
                fma2(acc[1][b], wb.x, xv.x); fma2(acc[1][b], wb.y, xv.y);
            }
        }
        const ulonglong2* u0 = (const ulonglong2*)(whh1 + (size_t)j0 * 128);
        const ulonglong2* u1 = (const ulonglong2*)(whh1 + (size_t)j1 * 128);
        #pragma unroll 4
        for (int k4 = 0; k4 < 32; k4++) {
            ulonglong2 wa = u0[k4], wb = u1[k4];
            #pragma unroll
            for (int b = 0; b < 4; b++) {
                ulonglong2 xv = *(const ulonglong2*)&s_h1[b][k4 * 4];
                fma2(acc[0][b], wa.x, xv.x); fma2(acc[0][b], wa.y, xv.y);
                fma2(acc[1][b], wb.x, xv.x); fma2(acc[1][b], wb.y, xv.y);
            }
        }
        float bias0 = bih1[j0] + bhh1[j0];
        float bias1 = bih1[j1] + bhh1[j1];
        #pragma unroll
        for (int b = 0; b < 4; b++) {
            s_g1[b][j0] = hsum2(acc[0][b]) + bias0;
            s_g1[b][j1] = hsum2(acc[1][b]) + bias1;
        }
    }
    __syncthreads();

    // lstm1 cell update (rows: 0..127=i, 128..255=f, 256..383=g, 384..511=o)
    #pragma unroll
    for (int i = 0; i < 2; i++) {
        int idx = tid + i * 256;
        int b = idx >> 7, k = idx & 127;
        float gi = s_g1[b][k],       gf = s_g1[b][128 + k];
        float gg = s_g1[b][256 + k], go = s_g1[b][384 + k];
        int gidx = (b0 + b) * H1n + k;
        float c = sigm(gf) * g_c1[gidx] + sigm(gi) * tanhf(gg);
        g_c1[gidx] = c;
        float h = sigm(go) * tanhf(c);
        g_h1[gidx] = h;
        s_h1n[b][k] = h;
    }
    __syncthreads();

    // lstm2 gates: thread = weight row tid (0..255), all 4 b
    {
        unsigned long long acc[4] = {};
        const ulonglong2* w = (const ulonglong2*)(wih2 + (size_t)tid * 128);
        #pragma unroll 4
        for (int k4 = 0; k4 < 32; k4++) {
            ulonglong2 wa = w[k4];
            #pragma unroll
            for (int b = 0; b < 4; b++) {
                ulonglong2 xv = *(const ulonglong2*)&s_h1n[b][k4 * 4];
                fma2(acc[b], wa.x, xv.x); fma2(acc[b], wa.y, xv.y);
            }
        }
        const ulonglong2* u = (const ulonglong2*)(whh2 + (size_t)tid * 64);
        #pragma unroll 4
        for (int k4 = 0; k4 < 16; k4++) {
            ulonglong2 wa = u[k4];
            #pragma unroll
            for (int b = 0; b < 4; b++) {
                ulonglong2 xv = *(const ulonglong2*)&s_h2[b][k4 * 4];
                fma2(acc[b], wa.x, xv.x); fma2(acc[b], wa.y, xv.y);
            }
        }
        float bias = bih2[tid] + bhh2[tid];
        #pragma unroll
        for (int b = 0; b < 4; b++) s_g2[b][tid] = hsum2(acc[b]) + bias;
    }
    __syncthreads();

    // lstm2 cell update: 4b x 64k
    {
        int b = tid >> 6, k = tid & 63;
        float gi = s_g2[b][k],       gf = s_g2[b][64 + k];
        float gg = s_g2[b][128 + k], go = s_g2[b][192 + k];
        int gidx = (b0 + b) * H2n + k;
        float c = sigm(gf) * g_c2[gidx] + sigm(gi) * tanhf(gg);
        g_c2[gidx] = c;
        float h = sigm(go) * tanhf(c);
        g_h2[gidx] = h;
        s_h2n[b][k] = h;
        g_x[(b0 + b) * 128 + k] = h;         // h2 half of pred input
    }
    __syncthreads();

    // query = h2_new @ wq^T + bq
    {
        int d = tid & 63, b = tid >> 6;
        unsigned long long acc = 0;
        const ulonglong2* w = (const ulonglong2*)(wq + (size_t)d * H2n);
        #pragma unroll
        for (int k4 = 0; k4 < 16; k4++) {
            ulonglong2 wa = w[k4];
            ulonglong2 xv = *(const ulonglong2*)&s_h2n[b][k4 * 4];
            fma2(acc, wa.x, xv.x); fma2(acc, wa.y, xv.y);
        }
        g_q[(b0 + b) * Dn + d] = hsum2(acc) + bq[d];
    }
}

// ---------------- attention: energy + masked softmax + context --------------
// grid 256 (one block per b), 256 threads
__global__ void __launch_bounds__(256) k_attn(
    const float* __restrict__ enc_key, const float* __restrict__ enc_val,
    const int* __restrict__ mask)
{
    __shared__ __align__(16) float s_q[64];
    __shared__ float s_w[512];
    __shared__ float s_red[40];
    __shared__ float s_p[4][64];
    const int b = blockIdx.x, tid = threadIdx.x;
    const int lane = tid & 31, warp = tid >> 5;

    if (tid < 64) s_q[tid] = g_q[b * Dn + tid];
    __syncthreads();

    // energy: 2 full 64-d dots per thread, 32 independent LDG.128
    float e0, e1;
    {
        const float4* qv = (const float4*)s_q;
        float4 q[16];
        #pragma unroll
        for (int j = 0; j < 16; j++) q[j] = qv[j];
        const float4* k0 = (const float4*)(enc_key + ((size_t)tid * Bn + b) * Dn);
        const float4* k1 = (const float4*)(enc_key + ((size_t)(tid + 256) * Bn + b) * Dn);
        float a0 = 0.f, a1 = 0.f;
        #pragma unroll
        for (int j = 0; j < 16; j++) {
            float4 ka = k0[j], kb = k1[j];
            a0 += ka.x * q[j].x + ka.y * q[j].y + ka.z * q[j].z + ka.w * q[j].w;
            a1 += kb.x * q[j].x + kb.y * q[j].y + kb.z * q[j].z + kb.w * q[j].w;
        }
        e0 = a0; e1 = a1;
    }
    // softmax over all t, then mask, then renorm (folded into one scale)
    float mx = fmaxf(e0, e1);
    #pragma unroll
    for (int o = 16; o; o >>= 1) mx = fmaxf(mx, __shfl_xor_sync(0xffffffffu, mx, o));
    if (lane == 0) s_red[warp] = mx;
    __syncthreads();
    if (tid == 0) {
        float m = s_red[0];
        #pragma unroll
        for (int i = 1; i < 8; i++) m = fmaxf(m, s_red[i]);
        s_red[32] = m;
    }
    __syncthreads();
    mx = s_red[32];
    int m0 = mask[(size_t)b * Tn + tid], m1 = mask[(size_t)b * Tn + tid + 256];
    float x0 = expf(e0 - mx), x1 = expf(e1 - mx);
    float s = x0 + x1, ws = (m0 ? x0 : 0.f) + (m1 ? x1 : 0.f);
    #pragma unroll
    for (int o = 16; o; o >>= 1) {
        s  += __shfl_xor_sync(0xffffffffu, s,  o);
        ws += __shfl_xor_sync(0xffffffffu, ws, o);
    }
    if (lane == 0) { s_red[warp] = s; s_red[8 + warp] = ws; }
    __syncthreads();
    if (tid == 0) {
        float S = 0.f, W = 0.f;
        #pragma unroll
        for (int i = 0; i < 8; i++) { S += s_red[i]; W += s_red[8 + i]; }
        s_red[33] = 1.0f / (S * fmaxf(W / S, 2e-30f));
    }
    __syncthreads();
    float inv = s_red[33];
    s_w[tid]       = m0 ? x0 * inv : 0.f;
    s_w[tid + 256] = m1 ? x1 * inv : 0.f;
    __syncthreads();

    // context: thread (d, chunk), 128 t per chunk, coalesced over d
    {
        int d = tid & 63, ch = tid >> 6;
        const float* vb = enc_val + (size_t)b * Dn + d;
        float a0 = 0.f, a1 = 0.f;
        #pragma unroll 4
        for (int t = ch * 128; t < ch * 128 + 128; t += 2) {
            a0 += s_w[t]     * vb[(size_t)t * (Bn * Dn)];
            a1 += s_w[t + 1] * vb[(size_t)(t + 1) * (Bn * Dn)];
        }
        s_p[ch][d] = a0 + a1;
    }
    __syncthreads();
    if (tid < 64) {
        float c = s_p[0][tid] + s_p[1][tid] + s_p[2][tid] + s_p[3][tid];
        g_x[b * 128 + 64 + tid] = c;         // ctx half of pred input
    }
}

// ---------------- pred GEMM (f32x2) + fused argmax --------------------------
// grid (79 v-tiles of 128, 8 b-tiles of 32), 256 threads, thread tile 4v x 4b
__global__ void __launch_bounds__(256) k_pred(const float* __restrict__ wp,
                                              const float* __restrict__ bp,
                                              float* __restrict__ out, int step) {
    __shared__ __align__(16) float s_x[32][128];
    const int tid = threadIdx.x;
    const int b0 = blockIdx.y * 32;

    for (int i = tid; i < 32 * 32; i += 256) {
        int bb = i >> 5, kq = i & 31;
        *(float4*)&s_x[bb][kq * 4] = *(const float4*)&g_x[(b0 + bb) * 128 + kq * 4];
    }
    __syncthreads();

    const int vg = tid & 31, bg = tid >> 5;
    const int v0 = blockIdx.x * 128 + vg * 4;
    const bool vok = v0 < Vn;                    // Vn % 4 == 0
    const int vl = vok ? v0 : 0;
    const ulonglong2* w0 = (const ulonglong2*)(wp + (size_t)(vl + 0) * 128);
    const ulonglong2* w1 = (const ulonglong2*)(wp + (size_t)(vl + 1) * 128);
    const ulonglong2* w2 = (const ulonglong2*)(wp + (size_t)(vl + 2) * 128);
    const ulonglong2* w3 = (const ulonglong2*)(wp + (size_t)(vl + 3) * 128);
    const int c0 = bg * 4;

    unsigned long long acc[4][4] = {};
    #pragma unroll 2
    for (int k4 = 0; k4 < 32; k4++) {
        ulonglong2 wa = w0[k4], wb = w1[k4], wc = w2[k4], wd = w3[k4];
        #pragma unroll
        for (int b = 0; b < 4; b++) {
            ulonglong2 xv = *(const ulonglong2*)&s_x[c0 + b][k4 * 4];
            fma2(acc[0][b], wa.x, xv.x); fma2(acc[0][b], wa.y, xv.y);
            fma2(acc[1][b], wb.x, xv.x); fma2(acc[1][b], wb.y, xv.y);
            fma2(acc[2][b], wc.x, xv.x); fma2(acc[2][b], wc.y, xv.y);
            fma2(acc[3][b], wd.x, xv.x); fma2(acc[3][b], wd.y, xv.y);
        }
    }

    float bs0 = 0.f, bs1 = 0.f, bs2 = 0.f, bs3 = 0.f;
    if (vok) {
        float4 b4 = *(const float4*)&bp[v0];
        bs0 = b4.x; bs1 = b4.y; bs2 = b4.z; bs3 = b4.w;
    }

    #pragma unroll
    for (int b = 0; b < 4; b++) {
        int bi = b0 + c0 + b;
        float r0 = hsum2(acc[0][b]) + bs0;
        float r1 = hsum2(acc[1][b]) + bs1;
        float r2 = hsum2(acc[2][b]) + bs2;
        float r3 = hsum2(acc[3][b]) + bs3;
        if (vok) {
            __stcs((float4*)(out + (size_t)bi * (ML * Vn) + (size_t)step * Vn + v0),
                   make_float4(r0, r1, r2, r3));
        }
        float best = r0; int bv = v0;
        if (r1 > best) { best = r1; bv = v0 + 1; }
        if (r2 > best) { best = r2; bv = v0 + 2; }
        if (r3 > best) { best = r3; bv = v0 + 3; }
        unsigned long long pk = vok
            ? ((unsigned long long)fkey(best) << 32) | (unsigned int)(~bv)
            : 0ull;
        #pragma unroll
        for (int o = 16; o; o >>= 1) {
            unsigned long long other = __shfl_down_sync(0xffffffffu, pk, o);
            if (other > pk) pk = other;
        }
        if (vg == 0) atomicMax(&g_amax[bi], pk);
    }
}

// ---------------- host: graph-capturable launch sequence --------------------
extern "C" void kernel_launch(void* const* d_in, const int* in_sizes, int n_in,
                              void* d_out, int out_size) {
    const float* enc_key = (const float*)d_in[0];
    const float* enc_val = (const float*)d_in[1];
    const int*   mask    = (const int*)d_in[2];
    const float* emb     = (const float*)d_in[3];
    const float* w_ih1   = (const float*)d_in[4];
    const float* w_hh1   = (const float*)d_in[5];
    const float* b_ih1   = (const float*)d_in[6];
    const float* b_hh1   = (const float*)d_in[7];
    const float* w_ih2   = (const float*)d_in[8];
    const float* w_hh2   = (const float*)d_in[9];
    const float* b_ih2   = (const float*)d_in[10];
    const float* b_hh2   = (const float*)d_in[11];
    const float* wq      = (const float*)d_in[12];
    const float* bq      = (const float*)d_in[13];
    const float* wp      = (const float*)d_in[14];
    const float* bp      = (const float*)d_in[15];
    float* out = (float*)d_out;

    k_init<<<128, 256>>>();
    for (int s = 0; s < ML; s++) {
        k_rnn<<<64, 256>>>(w_ih1, w_hh1, b_ih1, b_hh1,
                           w_ih2, w_hh2, b_ih2, b_hh2, wq, bq, emb);
        k_attn<<<256, 256>>>(enc_key, enc_val, mask);
        k_pred<<<dim3(79, 8), 256>>>(wp, bp, out, s);
    }
}

// round 5
// speedup vs baseline: 1.9929x; 1.8801x over previous
#include <cuda_runtime.h>

#define Bn   256
#define Tn   512
#define Dn   64
#define En   128
#define H1n  128
#define H2n  64
#define Vn   10000
#define ML   30
#define SOS_ 1
#define EOS_ 2

typedef unsigned long long ull;

// ---------------- persistent state + transposed weights (device globals) ----
__device__ float g_h1[Bn * H1n];
__device__ float g_c1[Bn * H1n];
__device__ float g_h2[Bn * H2n];
__device__ float g_c2[Bn * H2n];
__device__ float g_q[Bn * Dn];
__device__ float g_x[Bn * 128];            // [h2(64) | ctx(64)] pred input
__device__ ull   g_amax[Bn];               // packed (fkey(val)<<32 | ~v)

__device__ float g_w1T[320 * 512];         // [k][row]  k<192: wih1, k>=192: whh1
__device__ float g_w2T[192 * 256];         // [k][row]  k<128: wih2, k>=128: whh2
__device__ float g_wqT[64 * 64];           // [k][row]
__device__ float g_wpT[128 * Vn];          // [k][v]
__device__ float g_b1[512];
__device__ float g_b2[256];

__device__ __forceinline__ unsigned int fkey(float f) {
    unsigned int u = __float_as_uint(f);
    return (u & 0x80000000u) ? ~u : (u | 0x80000000u);
}
__device__ __forceinline__ float sigm(float x) { return 1.0f / (1.0f + expf(-x)); }

// packed fp32 pair FMA: d += a*b  (lanewise on (lo,hi))
__device__ __forceinline__ void fma2(ull& d, ull a, ull b) {
    asm("fma.rn.f32x2 %0, %1, %2, %0;" : "+l"(d) : "l"(a), "l"(b));
}
__device__ __forceinline__ ull dup2(float x) {
    unsigned int u = __float_as_uint(x); ull r;
    asm("mov.b64 %0, {%1, %1};" : "=l"(r) : "r"(u));
    return r;
}
__device__ __forceinline__ void unpk2(ull a, float& lo, float& hi) {
    unsigned int ul, uh;
    asm("mov.b64 {%0, %1}, %2;" : "=r"(ul), "=r"(uh) : "l"(a));
    lo = __uint_as_float(ul); hi = __uint_as_float(uh);
}

// ---------------- one-time prep: transpose weights to k-major ---------------
__global__ void k_prep_small(const float* __restrict__ wih1, const float* __restrict__ whh1,
                             const float* __restrict__ bih1, const float* __restrict__ bhh1,
                             const float* __restrict__ wih2, const float* __restrict__ whh2,
                             const float* __restrict__ bih2, const float* __restrict__ bhh2,
                             const float* __restrict__ wq) {
    int n = blockDim.x * gridDim.x;
    int t0 = blockIdx.x * blockDim.x + threadIdx.x;
    for (int i = t0; i < 320 * 512; i += n) {
        int k = i >> 9, r = i & 511;
        g_w1T[i] = (k < 192) ? wih1[r * 192 + k] : whh1[r * 128 + (k - 192)];
    }
    for (int i = t0; i < 192 * 256; i += n) {
        int k = i >> 8, r = i & 255;
        g_w2T[i] = (k < 128) ? wih2[r * 128 + k] : whh2[r * 64 + (k - 128)];
    }
    for (int i = t0; i < 64 * 64; i += n) {
        int k = i >> 6, r = i & 63;
        g_wqT[i] = wq[r * 64 + k];
    }
    for (int i = t0; i < 512; i += n) g_b1[i] = bih1[i] + bhh1[i];
    for (int i = t0; i < 256; i += n) g_b2[i] = bih2[i] + bhh2[i];
}

// tiled transpose wp[10000][128] -> wpT[128][10000]
__global__ void k_prep_wp(const float* __restrict__ wp) {
    __shared__ float t[32][33];
    int vt = blockIdx.x * 32, kt = blockIdx.y * 32;
    int tx = threadIdx.x & 31, ty = threadIdx.x >> 5;   // 32 x 8
    #pragma unroll
    for (int i = 0; i < 4; i++) {
        int v = vt + ty + i * 8;
        if (v < Vn) t[ty + i * 8][tx] = wp[(size_t)v * 128 + kt + tx];
    }
    __syncthreads();
    int v = vt + tx;
    if (v < Vn) {
        #pragma unroll
        for (int i = 0; i < 4; i++) {
            int k = kt + ty + i * 8;
            g_wpT[(size_t)k * Vn + v] = t[tx][ty + i * 8];
        }
    }
}

// ---------------- init ------------------------------------------------------
__global__ void k_init() {
    int i = blockIdx.x * blockDim.x + threadIdx.x;
    if (i < Bn * H1n) { g_h1[i] = 0.f; g_c1[i] = 0.f; }
    if (i < Bn * H2n) { g_h2[i] = 0.f; g_c2[i] = 0.f; }
    if (i < Bn * 128) g_x[i] = 0.f;
    if (i < Bn) g_amax[i] = (ull)(~(unsigned int)SOS_);
}

// ---------------- fused rnn: embed + lstm1 + lstm2 + query ------------------
// grid 64 (4 batch rows each), 256 threads. Row-pair FFMA2 from k-major weights.
__global__ void __launch_bounds__(256) k_rnn(const float* __restrict__ bq,
                                             const float* __restrict__ emb) {
    __shared__ __align__(16) ull  s_xd[4][192];    // dup pairs (emb|ctx)
    __shared__ __align__(16) ull  s_h1d[4][128];   // dup pairs h1 prev
    __shared__ __align__(16) float s_g1[4][512];
    __shared__ __align__(16) ull  s_h1nd[4][128];  // dup pairs h1 new
    __shared__ __align__(16) ull  s_h2d[4][64];    // dup pairs h2 prev
    __shared__ __align__(16) float s_g2[4][256];
    __shared__ __align__(16) ull  s_h2nd[4][64];   // dup pairs h2 new
    __shared__ int s_tok[4];

    const int tid = threadIdx.x;
    const int b0 = blockIdx.x * 4;

    if (tid < 4) {
        ull a = g_amax[b0 + tid];
        s_tok[tid] = (int)(~(unsigned int)(a & 0xFFFFFFFFull));
        g_amax[b0 + tid] = 0ull;
    }
    __syncthreads();

    for (int idx = tid; idx < 4 * 192; idx += 256) {
        int b = idx / 192, k = idx - b * 192;
        float v;
        if (k < En) {
            int tok = s_tok[b];
            v = (tok == EOS_) ? 0.f : emb[(size_t)tok * En + k];
        } else {
            v = g_x[(b0 + b) * 128 + 64 + (k - En)];
        }
        s_xd[b][k] = dup2(v);
    }
    for (int idx = tid; idx < 512; idx += 256) {
        int b = idx >> 7, k = idx & 127;
        s_h1d[b][k] = dup2(g_h1[(b0 + b) * H1n + k]);
    }
    { int b = tid >> 6, k = tid & 63; s_h2d[b][k] = dup2(g_h2[(b0 + b) * H2n + k]); }
    __syncthreads();

    // lstm1 gates: thread owns gate-row pair (2t, 2t+1), 4 b
    {
        const int r = 2 * tid;
        ull acc[4] = {};
        #pragma unroll 4
        for (int k = 0; k < 192; k++) {
            ull w = *(const ull*)&g_w1T[k * 512 + r];
            fma2(acc[0], w, s_xd[0][k]); fma2(acc[1], w, s_xd[1][k]);
            fma2(acc[2], w, s_xd[2][k]); fma2(acc[3], w, s_xd[3][k]);
        }
        #pragma unroll 4
        for (int k = 0; k < 128; k++) {
            ull w = *(const ull*)&g_w1T[(192 + k) * 512 + r];
            fma2(acc[0], w, s_h1d[0][k]); fma2(acc[1], w, s_h1d[1][k]);
            fma2(acc[2], w, s_h1d[2][k]); fma2(acc[3], w, s_h1d[3][k]);
        }
        float bl = g_b1[r], bh = g_b1[r + 1];
        #pragma unroll
        for (int b = 0; b < 4; b++) {
            float lo, hi; unpk2(acc[b], lo, hi);
            *(float2*)&s_g1[b][r] = make_float2(lo + bl, hi + bh);
        }
    }
    __syncthreads();

    // lstm1 cell update
    #pragma unroll
    for (int i = 0; i < 2; i++) {
        int idx = tid + i * 256;
        int b = idx >> 7, k = idx & 127;
        float gi = s_g1[b][k],       gf = s_g1[b][128 + k];
        float gg = s_g1[b][256 + k], go = s_g1[b][384 + k];
        int gidx = (b0 + b) * H1n + k;
        float c = sigm(gf) * g_c1[gidx] + sigm(gi) * tanhf(gg);
        g_c1[gidx] = c;
        float h = sigm(go) * tanhf(c);
        g_h1[gidx] = h;
        s_h1nd[b][k] = dup2(h);
    }
    __syncthreads();

    // lstm2 gates: threads 0..127 own row pair (2t, 2t+1), 4 b
    if (tid < 128) {
        const int r = 2 * tid;
        ull acc[4] = {};
        #pragma unroll 4
        for (int k = 0; k < 128; k++) {
            ull w = *(const ull*)&g_w2T[k * 256 + r];
            fma2(acc[0], w, s_h1nd[0][k]); fma2(acc[1], w, s_h1nd[1][k]);
            fma2(acc[2], w, s_h1nd[2][k]); fma2(acc[3], w, s_h1nd[3][k]);
        }
        #pragma unroll 4
        for (int k = 0; k < 64; k++) {
            ull w = *(const ull*)&g_w2T[(128 + k) * 256 + r];
            fma2(acc[0], w, s_h2d[0][k]); fma2(acc[1], w, s_h2d[1][k]);
            fma2(acc[2], w, s_h2d[2][k]); fma2(acc[3], w, s_h2d[3][k]);
        }
        float bl = g_b2[r], bh = g_b2[r + 1];
        #pragma unroll
        for (int b = 0; b < 4; b++) {
            float lo, hi; unpk2(acc[b], lo, hi);
            *(float2*)&s_g2[b][r] = make_float2(lo + bl, hi + bh);
        }
    }
    __syncthreads();

    // lstm2 cell update: 4b x 64k
    {
        int b = tid >> 6, k = tid & 63;
        float gi = s_g2[b][k],       gf = s_g2[b][64 + k];
        float gg = s_g2[b][128 + k], go = s_g2[b][192 + k];
        int gidx = (b0 + b) * H2n + k;
        float c = sigm(gf) * g_c2[gidx] + sigm(gi) * tanhf(gg);
        g_c2[gidx] = c;
        float h = sigm(go) * tanhf(c);
        g_h2[gidx] = h;
        s_h2nd[b][k] = dup2(h);
        g_x[(b0 + b) * 128 + k] = h;
    }
    __syncthreads();

    // query: threads 0..127: row pair (2p,2p+1) x 1 b
    if (tid < 128) {
        int p = tid & 31, b = tid >> 5;
        int r = 2 * p;
        ull acc = 0;
        #pragma unroll 8
        for (int k = 0; k < 64; k++) {
            ull w = *(const ull*)&g_wqT[k * 64 + r];
            fma2(acc, w, s_h2nd[b][k]);
        }
        float lo, hi; unpk2(acc, lo, hi);
        *(float2*)&g_q[(b0 + b) * Dn + r] = make_float2(lo + bq[r], hi + bq[r + 1]);
    }
}

// ---------------- attention: energy + masked softmax + context --------------
// grid 256 (one block per b), 256 threads
__global__ void __launch_bounds__(256) k_attn(
    const float* __restrict__ enc_key, const float* __restrict__ enc_val,
    const int* __restrict__ mask)
{
    __shared__ float s_e[512];
    __shared__ float s_w[512];
    __shared__ float s_red[40];
    __shared__ float s_p[4][64];
    const int b = blockIdx.x, tid = threadIdx.x;
    const int lane = tid & 31, warp = tid >> 5;

    // energy: thread = (slot, d-quarter); 8 t per thread, 4 LDG.128 per t
    {
        const int slot = tid >> 2, dq = tid & 3;
        const float4* qp = (const float4*)(g_q + b * Dn + dq * 16);
        float4 q0 = qp[0], q1 = qp[1], q2 = qp[2], q3 = qp[3];
        #pragma unroll 4
        for (int i = 0; i < 8; i++) {
            int t = slot + 64 * i;
            const float4* kp = (const float4*)(enc_key + ((size_t)t * Bn + b) * Dn + dq * 16);
            float4 a = kp[0], c = kp[1], d = kp[2], e = kp[3];
            float p = a.x * q0.x + a.y * q0.y + a.z * q0.z + a.w * q0.w
                    + c.x * q1.x + c.y * q1.y + c.z * q1.z + c.w * q1.w
                    + d.x * q2.x + d.y * q2.y + d.z * q2.z + d.w * q2.w
                    + e.x * q3.x + e.y * q3.y + e.z * q3.z + e.w * q3.w;
            p += __shfl_xor_sync(0xffffffffu, p, 1);
            p += __shfl_xor_sync(0xffffffffu, p, 2);
            if (dq == 0) s_e[t] = p;
        }
    }
    __syncthreads();

    // masked softmax (softmax over all t, mask, renorm folded into one scale)
    float e0 = s_e[tid], e1 = s_e[tid + 256];
    float mx = fmaxf(e0, e1);
    #pragma unroll
    for (int o = 16; o; o >>= 1) mx = fmaxf(mx, __shfl_xor_sync(0xffffffffu, mx, o));
    if (lane == 0) s_red[warp] = mx;
    __syncthreads();
    if (tid == 0) {
        float m = s_red[0];
        #pragma unroll
        for (int i = 1; i < 8; i++) m = fmaxf(m, s_red[i]);
        s_red[32] = m;
    }
    __syncthreads();
    mx = s_red[32];
    int m0 = mask[(size_t)b * Tn + tid], m1 = mask[(size_t)b * Tn + tid + 256];
    float x0 = expf(e0 - mx), x1 = expf(e1 - mx);
    float s = x0 + x1, ws = (m0 ? x0 : 0.f) + (m1 ? x1 : 0.f);
    #pragma unroll
    for (int o = 16; o; o >>= 1) {
        s  += __shfl_xor_sync(0xffffffffu, s,  o);
        ws += __shfl_xor_sync(0xffffffffu, ws, o);
    }
    if (lane == 0) { s_red[warp] = s; s_red[8 + warp] = ws; }
    __syncthreads();
    if (tid == 0) {
        float S = 0.f, W = 0.f;
        #pragma unroll
        for (int i = 0; i < 8; i++) { S += s_red[i]; W += s_red[8 + i]; }
        s_red[33] = 1.0f / (S * fmaxf(W / S, 2e-30f));
    }
    __syncthreads();
    float inv = s_red[33];
    s_w[tid]       = m0 ? x0 * inv : 0.f;
    s_w[tid + 256] = m1 ? x1 * inv : 0.f;
    __syncthreads();

    // context: thread (d, chunk), coalesced over d
    {
        int d = tid & 63, ch = tid >> 6;
        const float* vb = enc_val + (size_t)b * Dn + d;
        float a0 = 0.f, a1 = 0.f;
        #pragma unroll 4
        for (int t = ch * 128; t < ch * 128 + 128; t += 2) {
            a0 += s_w[t]     * vb[(size_t)t * (Bn * Dn)];
            a1 += s_w[t + 1] * vb[(size_t)(t + 1) * (Bn * Dn)];
        }
        s_p[ch][d] = a0 + a1;
    }
    __syncthreads();
    if (tid < 64) {
        float c = s_p[0][tid] + s_p[1][tid] + s_p[2][tid] + s_p[3][tid];
        g_x[b * 128 + 64 + tid] = c;
    }
}

// ---------------- pred GEMM (k-major, v-pair FFMA2) + fused argmax ----------
// grid (79 v-tiles of 128, 8 b-tiles of 32), 256 threads = 32 vq x 8 bq
__global__ void __launch_bounds__(256) k_pred(const float* __restrict__ bp,
                                              float* __restrict__ out, int step) {
    __shared__ __align__(16) ull   s_xd[32][128];   // dup pairs of x, 32 KB
    __shared__ __align__(16) float s_wt[16][128];   // staged wpT chunk, 8 KB
    const int tid = threadIdx.x;
    const int b0 = blockIdx.y * 32;
    const int vt = blockIdx.x;

    for (int idx = tid; idx < 32 * 128; idx += 256) {
        int b = idx >> 7, k = idx & 127;
        s_xd[b][k] = dup2(g_x[(b0 + b) * 128 + k]);
    }

    const int vq = tid & 31, bq = tid >> 5;
    const int v0 = vt * 128 + vq * 4;
    const bool vok = (v0 + 3) < Vn;

    ull acc0[4] = {}, acc1[4] = {};
    #pragma unroll 1
    for (int kc = 0; kc < 8; kc++) {
        __syncthreads();
        // stage 16 k-rows of wpT for this v-tile (coalesced)
        #pragma unroll
        for (int i = 0; i < 2; i++) {
            int idx = tid + i * 256;          // 512 float4 slots
            int kr = idx >> 5, j4 = idx & 31;
            int v = vt * 128 + j4 * 4;
            float4 val = make_float4(0.f, 0.f, 0.f, 0.f);
            if (v + 3 < Vn)
                val = *(const float4*)&g_wpT[(size_t)(kc * 16 + kr) * Vn + v];
            *(float4*)&s_wt[kr][j4 * 4] = val;
        }
        __syncthreads();
        #pragma unroll
        for (int kr = 0; kr < 16; kr++) {
            int k = kc * 16 + kr;
            ulonglong2 w = *(const ulonglong2*)&s_wt[kr][vq * 4];
            #pragma unroll
            for (int b = 0; b < 4; b++) {
                ull xd = s_xd[bq * 4 + b][k];
                fma2(acc0[b], w.x, xd);
                fma2(acc1[b], w.y, xd);
            }
        }
    }

    float bs0 = 0.f, bs1 = 0.f, bs2 = 0.f, bs3 = 0.f;
    if (vok) {
        float4 b4 = *(const float4*)&bp[v0];
        bs0 = b4.x; bs1 = b4.y; bs2 = b4.z; bs3 = b4.w;
    }

    #pragma unroll
    for (int b = 0; b < 4; b++) {
        int bi = b0 + bq * 4 + b;
        float r0, r1, r2, r3;
        unpk2(acc0[b], r0, r1);
        unpk2(acc1[b], r2, r3);
        r0 += bs0; r1 += bs1; r2 += bs2; r3 += bs3;
        if (vok) {
            __stcs((float4*)(out + (size_t)bi * (ML * Vn) + (size_t)step * Vn + v0),
                   make_float4(r0, r1, r2, r3));
        }
        float best = r0; int bv = v0;
        if (r1 > best) { best = r1; bv = v0 + 1; }
        if (r2 > best) { best = r2; bv = v0 + 2; }
        if (r3 > best) { best = r3; bv = v0 + 3; }
        ull pk = vok ? (((ull)fkey(best) << 32) | (unsigned int)(~bv)) : 0ull;
        #pragma unroll
        for (int o = 16; o; o >>= 1) {
            ull other = __shfl_down_sync(0xffffffffu, pk, o);
            if (other > pk) pk = other;
        }
        if (vq == 0) atomicMax(&g_amax[bi], pk);
    }
}

// ---------------- host: graph-capturable launch sequence --------------------
extern "C" void kernel_launch(void* const* d_in, const int* in_sizes, int n_in,
                              void* d_out, int out_size) {
    const float* enc_key = (const float*)d_in[0];
    const float* enc_val = (const float*)d_in[1];
    const int*   mask    = (const int*)d_in[2];
    const float* emb     = (const float*)d_in[3];
    const float* w_ih1   = (const float*)d_in[4];
    const float* w_hh1   = (const float*)d_in[5];
    const float* b_ih1   = (const float*)d_in[6];
    const float* b_hh1   = (const float*)d_in[7];
    const float* w_ih2   = (const float*)d_in[8];
    const float* w_hh2   = (const float*)d_in[9];
    const float* b_ih2   = (const float*)d_in[10];
    const float* b_hh2   = (const float*)d_in[11];
    const float* wq      = (const float*)d_in[12];
    const float* bq      = (const float*)d_in[13];
    const float* wp      = (const float*)d_in[14];
    const float* bp      = (const float*)d_in[15];
    float* out = (float*)d_out;

    k_prep_small<<<640, 256>>>(w_ih1, w_hh1, b_ih1, b_hh1,
                               w_ih2, w_hh2, b_ih2, b_hh2, wq);
    k_prep_wp<<<dim3(313, 4), 256>>>(wp);
    k_init<<<128, 256>>>();
    for (int s = 0; s < ML; s++) {
        k_rnn<<<64, 256>>>(bq, emb);
        k_attn<<<256, 256>>>(enc_key, enc_val, mask);
        k_pred<<<dim3(79, 8), 256>>>(bp, out, s);
    }
}

// round 6
// speedup vs baseline: 2.2030x; 1.1054x over previous
#include <cuda_runtime.h>

#define Bn   256
#define Tn   512
#define Dn   64
#define En   128
#define H1n  128
#define H2n  64
#define Vn   10000
#define ML   30
#define SOS_ 1
#define EOS_ 2

typedef unsigned long long ull;

// ---------------- persistent state + prepped weights (device globals) -------
__device__ float g_h1[2][Bn * H1n];        // ping-pong
__device__ float g_c1[Bn * H1n];
__device__ float g_h2[2][Bn * H2n];        // ping-pong
__device__ float g_c2[Bn * H2n];
__device__ float g_x[Bn * 128];            // [h2(64) | ctx(64)] pred input
__device__ ull   g_amax[Bn];               // packed (fkey(val)<<32 | ~v)

// k-major, gate-interleaved (col = 4*hdim + gate, gates i,f,g,o)
__device__ float g_w1R[320 * 512];         // k<192: wih1, k>=192: whh1
__device__ float g_w2R[192 * 256];         // k<128: wih2, k>=128: whh2
__device__ float g_b1R[512];
__device__ float g_b2R[256];
__device__ float g_wqT[64 * 64];           // [k][d]
__device__ float g_wpT[128 * Vn];          // [k][v]

__device__ __forceinline__ unsigned int fkey(float f) {
    unsigned int u = __float_as_uint(f);
    return (u & 0x80000000u) ? ~u : (u | 0x80000000u);
}
__device__ __forceinline__ float sigm(float x) { return 1.0f / (1.0f + expf(-x)); }

__device__ __forceinline__ void fma2(ull& d, ull a, ull b) {
    asm("fma.rn.f32x2 %0, %1, %2, %0;" : "+l"(d) : "l"(a), "l"(b));
}
__device__ __forceinline__ ull dup2(float x) {
    unsigned int u = __float_as_uint(x); ull r;
    asm("mov.b64 %0, {%1, %1};" : "=l"(r) : "r"(u));
    return r;
}
__device__ __forceinline__ void unpk2(ull a, float& lo, float& hi) {
    unsigned int ul, uh;
    asm("mov.b64 {%0, %1}, %2;" : "=r"(ul), "=r"(uh) : "l"(a));
    lo = __uint_as_float(ul); hi = __uint_as_float(uh);
}

// ---------------- one-time prep ---------------------------------------------
__global__ void k_prep_small(const float* __restrict__ wih1, const float* __restrict__ whh1,
                             const float* __restrict__ bih1, const float* __restrict__ bhh1,
                             const float* __restrict__ wih2, const float* __restrict__ whh2,
                             const float* __restrict__ bih2, const float* __restrict__ bhh2,
                             const float* __restrict__ wq) {
    int n = blockDim.x * gridDim.x;
    int t0 = blockIdx.x * blockDim.x + threadIdx.x;
    for (int i = t0; i < 320 * 512; i += n) {
        int k = i >> 9, c = i & 511;
        int h = c >> 2, g = c & 3, r = g * 128 + h;
        g_w1R[i] = (k < 192) ? wih1[r * 192 + k] : whh1[r * 128 + (k - 192)];
    }
    for (int i = t0; i < 192 * 256; i += n) {
        int k = i >> 8, c = i & 255;
        int h = c >> 2, g = c & 3, r = g * 64 + h;
        g_w2R[i] = (k < 128) ? wih2[r * 128 + k] : whh2[r * 64 + (k - 128)];
    }
    for (int i = t0; i < 64 * 64; i += n) {
        int k = i >> 6, d = i & 63;
        g_wqT[i] = wq[d * 64 + k];
    }
    for (int c = t0; c < 512; c += n) {
        int h = c >> 2, g = c & 3, r = g * 128 + h;
        g_b1R[c] = bih1[r] + bhh1[r];
    }
    for (int c = t0; c < 256; c += n) {
        int h = c >> 2, g = c & 3, r = g * 64 + h;
        g_b2R[c] = bih2[r] + bhh2[r];
    }
}

// tiled transpose wp[10000][128] -> wpT[128][10000]
__global__ void k_prep_wp(const float* __restrict__ wp) {
    __shared__ float t[32][33];
    int vt = blockIdx.x * 32, kt = blockIdx.y * 32;
    int tx = threadIdx.x & 31, ty = threadIdx.x >> 5;   // 32 x 8
    #pragma unroll
    for (int i = 0; i < 4; i++) {
        int v = vt + ty + i * 8;
        if (v < Vn) t[ty + i * 8][tx] = wp[(size_t)v * 128 + kt + tx];
    }
    __syncthreads();
    int v = vt + tx;
    if (v < Vn) {
        #pragma unroll
        for (int i = 0; i < 4; i++) {
            int k = kt + ty + i * 8;
            g_wpT[(size_t)k * Vn + v] = t[tx][ty + i * 8];
        }
    }
}

__global__ void k_init() {
    int i = blockIdx.x * blockDim.x + threadIdx.x;
    if (i < Bn * H1n) { g_h1[0][i] = 0.f; g_h1[1][i] = 0.f; g_c1[i] = 0.f; }
    if (i < Bn * H2n) { g_h2[0][i] = 0.f; g_h2[1][i] = 0.f; g_c2[i] = 0.f; }
    if (i < Bn * 128) g_x[i] = 0.f;
    if (i < Bn) g_amax[i] = (ull)(~(unsigned int)SOS_);
}

// ---------------- k_lstm1: grid (8 rowtiles, 8 btiles), 256 thr -------------
// block: 64 rows' (16 hdims) x 32 b, k=320; smem-staged dup'd weights.
#define L1_SWD   0
#define L1_SX    32768
#define L1_SG    (32768 + 320 * 36 * 4)          // 32768 + 46080
#define L1_TOK   (L1_SG + 64 * 34 * 4)           // + 8704
#define L1_SMEM  (L1_TOK + 128)

__global__ void __launch_bounds__(256) k_lstm1(const float* __restrict__ emb, int p) {
    extern __shared__ __align__(16) char sm[];
    ull   (*s_wd)[32][64] = (ull(*)[32][64])(sm + L1_SWD);   // [2][32][64]
    float (*s_x)[36]      = (float(*)[36])(sm + L1_SX);      // [320][36]
    float (*s_g)[34]      = (float(*)[34])(sm + L1_SG);      // [64][34]
    int*  s_tok           = (int*)(sm + L1_TOK);

    const int tid = threadIdx.x;
    const int rt = blockIdx.x, bt = blockIdx.y;
    const int r0 = rt * 64, b0 = bt * 32;
    const int lane = tid & 31, warp = tid >> 5;
    const float* __restrict__ h1old = g_h1[p];
    float* __restrict__ h1new = g_h1[p ^ 1];

    if (tid < 32) {
        ull a = g_amax[b0 + tid];
        s_tok[tid] = (int)(~(unsigned int)(a & 0xFFFFFFFFull));
    }
    __syncthreads();

    // x fill: warp w handles k in [40w, 40w+40), lane = b
    for (int k = warp * 40; k < warp * 40 + 40; k++) {
        int b = lane;
        float v;
        if (k < 128) {
            int t = s_tok[b];
            v = (t == EOS_) ? 0.f : emb[(size_t)t * En + k];
        } else if (k < 192) {
            v = g_x[(b0 + b) * 128 + 64 + (k - 128)];
        } else {
            v = h1old[(b0 + b) * H1n + (k - 192)];
        }
        s_x[k][b] = v;
    }

    // prefetch chunk 0 weights
    float4 pw0, pw1;
    {
        int i0 = tid, i1 = tid + 256;
        pw0 = *(const float4*)&g_w1R[(size_t)(i0 >> 4) * 512 + r0 + (i0 & 15) * 4];
        pw1 = *(const float4*)&g_w1R[(size_t)(i1 >> 4) * 512 + r0 + (i1 & 15) * 4];
    }
    __syncthreads();
    {
        int i0 = tid, i1 = tid + 256;
        *(ulonglong2*)&s_wd[0][i0 >> 4][(i0 & 15) * 4]     = make_ulonglong2(dup2(pw0.x), dup2(pw0.y));
        *(ulonglong2*)&s_wd[0][i0 >> 4][(i0 & 15) * 4 + 2] = make_ulonglong2(dup2(pw0.z), dup2(pw0.w));
        *(ulonglong2*)&s_wd[0][i1 >> 4][(i1 & 15) * 4]     = make_ulonglong2(dup2(pw1.x), dup2(pw1.y));
        *(ulonglong2*)&s_wd[0][i1 >> 4][(i1 & 15) * 4 + 2] = make_ulonglong2(dup2(pw1.z), dup2(pw1.w));
    }
    __syncthreads();

    const int R = tid >> 3, Bg = tid & 7;     // 32 rowgroups(2) x 8 bgroups(4)
    ull a00 = 0, a01 = 0, a10 = 0, a11 = 0;

    for (int c = 0; c < 10; c++) {
        if (c < 9) {
            int kb = (c + 1) * 32;
            int i0 = tid, i1 = tid + 256;
            pw0 = *(const float4*)&g_w1R[(size_t)(kb + (i0 >> 4)) * 512 + r0 + (i0 & 15) * 4];
            pw1 = *(const float4*)&g_w1R[(size_t)(kb + (i1 >> 4)) * 512 + r0 + (i1 & 15) * 4];
        }
        const ull* wb = &s_wd[c & 1][0][0];
        #pragma unroll
        for (int kk = 0; kk < 32; kk++) {
            ulonglong2 w  = *(const ulonglong2*)(wb + kk * 64 + 2 * R);
            ulonglong2 xp = *(const ulonglong2*)&s_x[c * 32 + kk][Bg * 4];
            fma2(a00, w.x, xp.x); fma2(a01, w.x, xp.y);
            fma2(a10, w.y, xp.x); fma2(a11, w.y, xp.y);
        }
        __syncthreads();
        if (c < 9) {
            int nb = (c + 1) & 1;
            int i0 = tid, i1 = tid + 256;
            *(ulonglong2*)&s_wd[nb][i0 >> 4][(i0 & 15) * 4]     = make_ulonglong2(dup2(pw0.x), dup2(pw0.y));
            *(ulonglong2*)&s_wd[nb][i0 >> 4][(i0 & 15) * 4 + 2] = make_ulonglong2(dup2(pw0.z), dup2(pw0.w));
            *(ulonglong2*)&s_wd[nb][i1 >> 4][(i1 & 15) * 4]     = make_ulonglong2(dup2(pw1.x), dup2(pw1.y));
            *(ulonglong2*)&s_wd[nb][i1 >> 4][(i1 & 15) * 4 + 2] = make_ulonglong2(dup2(pw1.z), dup2(pw1.w));
        }
        __syncthreads();
    }

    // gates -> smem with bias
    {
        float bl = g_b1R[r0 + 2 * R], bh = g_b1R[r0 + 2 * R + 1];
        float v0, v1;
        unpk2(a00, v0, v1); s_g[2 * R][Bg * 4] = v0 + bl; s_g[2 * R][Bg * 4 + 1] = v1 + bl;
        unpk2(a01, v0, v1); s_g[2 * R][Bg * 4 + 2] = v0 + bl; s_g[2 * R][Bg * 4 + 3] = v1 + bl;
        unpk2(a10, v0, v1); s_g[2 * R + 1][Bg * 4] = v0 + bh; s_g[2 * R + 1][Bg * 4 + 1] = v1 + bh;
        unpk2(a11, v0, v1); s_g[2 * R + 1][Bg * 4 + 2] = v0 + bh; s_g[2 * R + 1][Bg * 4 + 3] = v1 + bh;
    }
    __syncthreads();

    // cell update: 16 hdims x 32 b
    #pragma unroll
    for (int t = 0; t < 2; t++) {
        int i = tid + t * 256;
        int b = i & 31, hl = i >> 5;
        float gi = s_g[4 * hl][b],     gf = s_g[4 * hl + 1][b];
        float gg = s_g[4 * hl + 2][b], go = s_g[4 * hl + 3][b];
        int gidx = (b0 + b) * H1n + rt * 16 + hl;
        float c = sigm(gf) * g_c1[gidx] + sigm(gi) * tanhf(gg);
        g_c1[gidx] = c;
        h1new[gidx] = sigm(go) * tanhf(c);
    }
}

// ---------------- k_lstm2: grid (4 rowtiles, 8 btiles), 256 thr -------------
#define L2_SWD   0
#define L2_SX    32768
#define L2_SG    (32768 + 192 * 36 * 4)          // 32768 + 27648
#define L2_SMEM  (L2_SG + 64 * 34 * 4)           // + 8704

__global__ void __launch_bounds__(256) k_lstm2(int p) {
    extern __shared__ __align__(16) char sm[];
    ull   (*s_wd)[32][64] = (ull(*)[32][64])(sm + L2_SWD);
    float (*s_x)[36]      = (float(*)[36])(sm + L2_SX);      // [192][36]
    float (*s_g)[34]      = (float(*)[34])(sm + L2_SG);

    const int tid = threadIdx.x;
    const int rt = blockIdx.x, bt = blockIdx.y;
    const int r0 = rt * 64, b0 = bt * 32;
    const int lane = tid & 31, warp = tid >> 5;
    const float* __restrict__ h1new = g_h1[p ^ 1];
    const float* __restrict__ h2old = g_h2[p];
    float* __restrict__ h2new = g_h2[p ^ 1];

    for (int k = warp * 24; k < warp * 24 + 24; k++) {
        int b = lane;
        float v = (k < 128) ? h1new[(b0 + b) * H1n + k]
                            : h2old[(b0 + b) * H2n + (k - 128)];
        s_x[k][b] = v;
    }

    float4 pw0, pw1;
    {
        int i0 = tid, i1 = tid + 256;
        pw0 = *(const float4*)&g_w2R[(size_t)(i0 >> 4) * 256 + r0 + (i0 & 15) * 4];
        pw1 = *(const float4*)&g_w2R[(size_t)(i1 >> 4) * 256 + r0 + (i1 & 15) * 4];
    }
    __syncthreads();
    {
        int i0 = tid, i1 = tid + 256;
        *(ulonglong2*)&s_wd[0][i0 >> 4][(i0 & 15) * 4]     = make_ulonglong2(dup2(pw0.x), dup2(pw0.y));
        *(ulonglong2*)&s_wd[0][i0 >> 4][(i0 & 15) * 4 + 2] = make_ulonglong2(dup2(pw0.z), dup2(pw0.w));
        *(ulonglong2*)&s_wd[0][i1 >> 4][(i1 & 15) * 4]     = make_ulonglong2(dup2(pw1.x), dup2(pw1.y));
        *(ulonglong2*)&s_wd[0][i1 >> 4][(i1 & 15) * 4 + 2] = make_ulonglong2(dup2(pw1.z), dup2(pw1.w));
    }
    __syncthreads();

    const int R = tid >> 3, Bg = tid & 7;
    ull a00 = 0, a01 = 0, a10 = 0, a11 = 0;

    for (int c = 0; c < 6; c++) {
        if (c < 5) {
            int kb = (c + 1) * 32;
            int i0 = tid, i1 = tid + 256;
            pw0 = *(const float4*)&g_w2R[(size_t)(kb + (i0 >> 4)) * 256 + r0 + (i0 & 15) * 4];
            pw1 = *(const float4*)&g_w2R[(size_t)(kb + (i1 >> 4)) * 256 + r0 + (i1 & 15) * 4];
        }
        const ull* wb = &s_wd[c & 1][0][0];
        #pragma unroll
        for (int kk = 0; kk < 32; kk++) {
            ulonglong2 w  = *(const ulonglong2*)(wb + kk * 64 + 2 * R);
            ulonglong2 xp = *(const ulonglong2*)&s_x[c * 32 + kk][Bg * 4];
            fma2(a00, w.x, xp.x); fma2(a01, w.x, xp.y);
            fma2(a10, w.y, xp.x); fma2(a11, w.y, xp.y);
        }
        __syncthreads();
        if (c < 5) {
            int nb = (c + 1) & 1;
            int i0 = tid, i1 = tid + 256;
            *(ulonglong2*)&s_wd[nb][i0 >> 4][(i0 & 15) * 4]     = make_ulonglong2(dup2(pw0.x), dup2(pw0.y));
            *(ulonglong2*)&s_wd[nb][i0 >> 4][(i0 & 15) * 4 + 2] = make_ulonglong2(dup2(pw0.z), dup2(pw0.w));
            *(ulonglong2*)&s_wd[nb][i1 >> 4][(i1 & 15) * 4]     = make_ulonglong2(dup2(pw1.x), dup2(pw1.y));
            *(ulonglong2*)&s_wd[nb][i1 >> 4][(i1 & 15) * 4 + 2] = make_ulonglong2(dup2(pw1.z), dup2(pw1.w));
        }
        __syncthreads();
    }

    {
        float bl = g_b2R[r0 + 2 * R], bh = g_b2R[r0 + 2 * R + 1];
        float v0, v1;
        unpk2(a00, v0, v1); s_g[2 * R][Bg * 4] = v0 + bl; s_g[2 * R][Bg * 4 + 1] = v1 + bl;
        unpk2(a01, v0, v1); s_g[2 * R][Bg * 4 + 2] = v0 + bl; s_g[2 * R][Bg * 4 + 3] = v1 + bl;
        unpk2(a10, v0, v1); s_g[2 * R + 1][Bg * 4] = v0 + bh; s_g[2 * R + 1][Bg * 4 + 1] = v1 + bh;
        unpk2(a11, v0, v1); s_g[2 * R + 1][Bg * 4 + 2] = v0 + bh; s_g[2 * R + 1][Bg * 4 + 3] = v1 + bh;
    }
    __syncthreads();

    #pragma unroll
    for (int t = 0; t < 2; t++) {
        int i = tid + t * 256;
        int b = i & 31, hl = i >> 5;
        float gi = s_g[4 * hl][b],     gf = s_g[4 * hl + 1][b];
        float gg = s_g[4 * hl + 2][b], go = s_g[4 * hl + 3][b];
        int gidx = (b0 + b) * H2n + rt * 16 + hl;
        float c = sigm(gf) * g_c2[gidx] + sigm(gi) * tanhf(gg);
        g_c2[gidx] = c;
        float h = sigm(go) * tanhf(c);
        h2new[gidx] = h;
        g_x[(b0 + b) * 128 + rt * 16 + hl] = h;
    }
}

// ---------------- attention: query + energy + masked softmax + context ------
// grid 256 (one block per b), 256 threads. Also resets g_amax[b].
__global__ void __launch_bounds__(256) k_attn(
    const float* __restrict__ enc_key, const float* __restrict__ enc_val,
    const int* __restrict__ mask, const float* __restrict__ bq)
{
    __shared__ __align__(16) float s_q[64];
    __shared__ float s_h2[64];
    __shared__ float s_qp[4][64];
    __shared__ float s_e[512];
    __shared__ float s_w[512];
    __shared__ float s_red[40];
    __shared__ float s_p[4][64];
    const int b = blockIdx.x, tid = threadIdx.x;
    const int lane = tid & 31, warp = tid >> 5;

    if (tid == 0) g_amax[b] = 0ull;
    if (tid < 64) s_h2[tid] = g_x[b * 128 + tid];
    __syncthreads();

    // query = h2 @ wqT + bq
    {
        int d = tid & 63, kq = tid >> 6;
        float a = 0.f;
        #pragma unroll
        for (int k = kq * 16; k < kq * 16 + 16; k++)
            a += g_wqT[k * 64 + d] * s_h2[k];
        s_qp[kq][d] = a;
    }
    __syncthreads();
    if (tid < 64)
        s_q[tid] = s_qp[0][tid] + s_qp[1][tid] + s_qp[2][tid] + s_qp[3][tid] + bq[tid];
    __syncthreads();

    // energy: thread = (slot, d-quarter); 8 t per thread, 4 LDG.128 per t
    {
        const int slot = tid >> 2, dq = tid & 3;
        const float4* qp = (const float4*)(s_q + dq * 16);
        float4 q0 = qp[0], q1 = qp[1], q2 = qp[2], q3 = qp[3];
        #pragma unroll 4
        for (int i = 0; i < 8; i++) {
            int t = slot + 64 * i;
            const float4* kp = (const float4*)(enc_key + ((size_t)t * Bn + b) * Dn + dq * 16);
            float4 a = kp[0], c = kp[1], d = kp[2], e = kp[3];
            float pp = a.x * q0.x + a.y * q0.y + a.z * q0.z + a.w * q0.w
                     + c.x * q1.x + c.y * q1.y + c.z * q1.z + c.w * q1.w
                     + d.x * q2.x + d.y * q2.y + d.z * q2.z + d.w * q2.w
                     + e.x * q3.x + e.y * q3.y + e.z * q3.z + e.w * q3.w;
            pp += __shfl_xor_sync(0xffffffffu, pp, 1);
            pp += __shfl_xor_sync(0xffffffffu, pp, 2);
            if (dq == 0) s_e[t] = pp;
        }
    }
    __syncthreads();

    float e0 = s_e[tid], e1 = s_e[tid + 256];
    float mx = fmaxf(e0, e1);
    #pragma unroll
    for (int o = 16; o; o >>= 1) mx = fmaxf(mx, __shfl_xor_sync(0xffffffffu, mx, o));
    if (lane == 0) s_red[warp] = mx;
    __syncthreads();
    if (tid == 0) {
        float m = s_red[0];
        #pragma unroll
        for (int i = 1; i < 8; i++) m = fmaxf(m, s_red[i]);
        s_red[32] = m;
    }
    __syncthreads();
    mx = s_red[32];
    int m0 = mask[(size_t)b * Tn + tid], m1 = mask[(size_t)b * Tn + tid + 256];
    float x0 = expf(e0 - mx), x1 = expf(e1 - mx);
    float s = x0 + x1, ws = (m0 ? x0 : 0.f) + (m1 ? x1 : 0.f);
    #pragma unroll
    for (int o = 16; o; o >>= 1) {
        s  += __shfl_xor_sync(0xffffffffu, s,  o);
        ws += __shfl_xor_sync(0xffffffffu, ws, o);
    }
    if (lane == 0) { s_red[warp] = s; s_red[8 + warp] = ws; }
    __syncthreads();
    if (tid == 0) {
        float S = 0.f, W = 0.f;
        #pragma unroll
        for (int i = 0; i < 8; i++) { S += s_red[i]; W += s_red[8 + i]; }
        s_red[33] = 1.0f / (S * fmaxf(W / S, 2e-30f));
    }
    __syncthreads();
    float inv = s_red[33];
    s_w[tid]       = m0 ? x0 * inv : 0.f;
    s_w[tid + 256] = m1 ? x1 * inv : 0.f;
    __syncthreads();

    {
        int d = tid & 63, ch = tid >> 6;
        const float* vb = enc_val + (size_t)b * Dn + d;
        float a0 = 0.f, a1 = 0.f;
        #pragma unroll 4
        for (int t = ch * 128; t < ch * 128 + 128; t += 2) {
            a0 += s_w[t]     * vb[(size_t)t * (Bn * Dn)];
            a1 += s_w[t + 1] * vb[(size_t)(t + 1) * (Bn * Dn)];
        }
        s_p[ch][d] = a0 + a1;
    }
    __syncthreads();
    if (tid < 64) {
        float c = s_p[0][tid] + s_p[1][tid] + s_p[2][tid] + s_p[3][tid];
        g_x[b * 128 + 64 + tid] = c;
    }
}

// ---------------- pred GEMM (k-major, v-pair FFMA2) + fused argmax ----------
__global__ void __launch_bounds__(256) k_pred(const float* __restrict__ bp,
                                              float* __restrict__ out, int step) {
    __shared__ __align__(16) ull   s_xd[32][128];
    __shared__ __align__(16) float s_wt[16][128];
    const int tid = threadIdx.x;
    const int b0 = blockIdx.y * 32;
    const int vt = blockIdx.x;

    for (int idx = tid; idx < 32 * 128; idx += 256) {
        int b = idx >> 7, k = idx & 127;
        s_xd[b][k] = dup2(g_x[(b0 + b) * 128 + k]);
    }

    const int vq = tid & 31, bq = tid >> 5;
    const int v0 = vt * 128 + vq * 4;
    const bool vok = (v0 + 3) < Vn;

    ull acc0[4] = {}, acc1[4] = {};
    #pragma unroll 1
    for (int kc = 0; kc < 8; kc++) {
        __syncthreads();
        #pragma unroll
        for (int i = 0; i < 2; i++) {
            int idx = tid + i * 256;
            int kr = idx >> 5, j4 = idx & 31;
            int v = vt * 128 + j4 * 4;
            float4 val = make_float4(0.f, 0.f, 0.f, 0.f);
            if (v + 3 < Vn)
                val = *(const float4*)&g_wpT[(size_t)(kc * 16 + kr) * Vn + v];
            *(float4*)&s_wt[kr][j4 * 4] = val;
        }
        __syncthreads();
        #pragma unroll
        for (int kr = 0; kr < 16; kr++) {
            int k = kc * 16 + kr;
            ulonglong2 w = *(const ulonglong2*)&s_wt[kr][vq * 4];
            #pragma unroll
            for (int b = 0; b < 4; b++) {
                ull xd = s_xd[bq * 4 + b][k];
                fma2(acc0[b], w.x, xd);
                fma2(acc1[b], w.y, xd);
            }
        }
    }

    float bs0 = 0.f, bs1 = 0.f, bs2 = 0.f, bs3 = 0.f;
    if (vok) {
        float4 b4 = *(const float4*)&bp[v0];
        bs0 = b4.x; bs1 = b4.y; bs2 = b4.z; bs3 = b4.w;
    }

    #pragma unroll
    for (int b = 0; b < 4; b++) {
        int bi = b0 + bq * 4 + b;
        float r0, r1, r2, r3;
        unpk2(acc0[b], r0, r1);
        unpk2(acc1[b], r2, r3);
        r0 += bs0; r1 += bs1; r2 += bs2; r3 += bs3;
        if (vok) {
            __stcs((float4*)(out + (size_t)bi * (ML * Vn) + (size_t)step * Vn + v0),
                   make_float4(r0, r1, r2, r3));
        }
        float best = r0; int bv = v0;
        if (r1 > best) { best = r1; bv = v0 + 1; }
        if (r2 > best) { best = r2; bv = v0 + 2; }
        if (r3 > best) { best = r3; bv = v0 + 3; }
        ull pk = vok ? (((ull)fkey(best) << 32) | (unsigned int)(~bv)) : 0ull;
        #pragma unroll
        for (int o = 16; o; o >>= 1) {
            ull other = __shfl_down_sync(0xffffffffu, pk, o);
            if (other > pk) pk = other;
        }
        if (vq == 0) atomicMax(&g_amax[bi], pk);
    }
}

// ---------------- host ------------------------------------------------------
extern "C" void kernel_launch(void* const* d_in, const int* in_sizes, int n_in,
                              void* d_out, int out_size) {
    const float* enc_key = (const float*)d_in[0];
    const float* enc_val = (const float*)d_in[1];
    const int*   mask    = (const int*)d_in[2];
    const float* emb     = (const float*)d_in[3];
    const float* w_ih1   = (const float*)d_in[4];
    const float* w_hh1   = (const float*)d_in[5];
    const float* b_ih1   = (const float*)d_in[6];
    const float* b_hh1   = (const float*)d_in[7];
    const float* w_ih2   = (const float*)d_in[8];
    const float* w_hh2   = (const float*)d_in[9];
    const float* b_ih2   = (const float*)d_in[10];
    const float* b_hh2   = (const float*)d_in[11];
    const float* wq      = (const float*)d_in[12];
    const float* bq      = (const float*)d_in[13];
    const float* wp      = (const float*)d_in[14];
    const float* bp      = (const float*)d_in[15];
    float* out = (float*)d_out;

    static int s_attr_done = 0;
    if (!s_attr_done) {
        cudaFuncSetAttribute(k_lstm1, cudaFuncAttributeMaxDynamicSharedMemorySize, L1_SMEM);
        cudaFuncSetAttribute(k_lstm2, cudaFuncAttributeMaxDynamicSharedMemorySize, L2_SMEM);
        s_attr_done = 1;
    }

    k_prep_small<<<640, 256>>>(w_ih1, w_hh1, b_ih1, b_hh1,
                               w_ih2, w_hh2, b_ih2, b_hh2, wq);
    k_prep_wp<<<dim3(313, 4), 256>>>(wp);
    k_init<<<128, 256>>>();
    for (int s = 0; s < ML; s++) {
        int p = s & 1;
        k_lstm1<<<dim3(8, 8), 256, L1_SMEM>>>(emb, p);
        k_lstm2<<<dim3(4, 8), 256, L2_SMEM>>>(p);
        k_attn<<<256, 256>>>(enc_key, enc_val, mask, bq);
        k_pred<<<dim3(79, 8), 256>>>(bp, out, s);
    }
}

// round 7
// speedup vs baseline: 2.4866x; 1.1287x over previous
#include <cuda_runtime.h>

#define Bn   256
#define Tn   512
#define Dn   64
#define En   128
#define H1n  128
#define H2n  64
#define Vn   10000
#define ML   30
#define SOS_ 1
#define EOS_ 2

typedef unsigned long long ull;

// ---------------- persistent state + prepped weights (device globals) -------
__device__ float g_h1[2][Bn * H1n];        // ping-pong
__device__ float g_c1[Bn * H1n];
__device__ float g_h2[2][Bn * H2n];        // ping-pong
__device__ float g_c2[Bn * H2n];
__device__ float g_x[Bn * 128];            // [h2(64) | ctx(64)] pred input
__device__ ull   g_amax[Bn];               // packed (fkey(val)<<32 | ~v)

// k-major, gate-interleaved (col = 4*hdim + gate, gates i,f,g,o)
__device__ float g_w1R[320 * 512];         // k<192: wih1, k>=192: whh1
__device__ float g_w2R[192 * 256];         // k<128: wih2, k>=128: whh2
__device__ float g_b1R[512];
__device__ float g_b2R[256];
__device__ float g_wqT[64 * 64];           // [k][d]
__device__ float g_wpT[128 * Vn];          // [k][v]

__device__ __forceinline__ unsigned int fkey(float f) {
    unsigned int u = __float_as_uint(f);
    return (u & 0x80000000u) ? ~u : (u | 0x80000000u);
}
__device__ __forceinline__ float sigm(float x) { return 1.0f / (1.0f + expf(-x)); }

__device__ __forceinline__ void fma2(ull& d, ull a, ull b) {
    asm("fma.rn.f32x2 %0, %1, %2, %0;" : "+l"(d) : "l"(a), "l"(b));
}
__device__ __forceinline__ ull dup2(float x) {
    unsigned int u = __float_as_uint(x); ull r;
    asm("mov.b64 %0, {%1, %1};" : "=l"(r) : "r"(u));
    return r;
}
__device__ __forceinline__ void unpk2(ull a, float& lo, float& hi) {
    unsigned int ul, uh;
    asm("mov.b64 {%0, %1}, %2;" : "=r"(ul), "=r"(uh) : "l"(a));
    lo = __uint_as_float(ul); hi = __uint_as_float(uh);
}

// ---------------- one-time prep ---------------------------------------------
__global__ void k_prep_small(const float* __restrict__ wih1, const float* __restrict__ whh1,
                             const float* __restrict__ bih1, const float* __restrict__ bhh1,
                             const float* __restrict__ wih2, const float* __restrict__ whh2,
                             const float* __restrict__ bih2, const float* __restrict__ bhh2,
                             const float* __restrict__ wq) {
    int n = blockDim.x * gridDim.x;
    int t0 = blockIdx.x * blockDim.x + threadIdx.x;
    for (int i = t0; i < 320 * 512; i += n) {
        int k = i >> 9, c = i & 511;
        int h = c >> 2, g = c & 3, r = g * 128 + h;
        g_w1R[i] = (k < 192) ? wih1[r * 192 + k] : whh1[r * 128 + (k - 192)];
    }
    for (int i = t0; i < 192 * 256; i += n) {
        int k = i >> 8, c = i & 255;
        int h = c >> 2, g = c & 3, r = g * 64 + h;
        g_w2R[i] = (k < 128) ? wih2[r * 128 + k] : whh2[r * 64 + (k - 128)];
    }
    for (int i = t0; i < 64 * 64; i += n) {
        int k = i >> 6, d = i & 63;
        g_wqT[i] = wq[d * 64 + k];
    }
    for (int c = t0; c < 512; c += n) {
        int h = c >> 2, g = c & 3, r = g * 128 + h;
        g_b1R[c] = bih1[r] + bhh1[r];
    }
    for (int c = t0; c < 256; c += n) {
        int h = c >> 2, g = c & 3, r = g * 64 + h;
        g_b2R[c] = bih2[r] + bhh2[r];
    }
}

// tiled transpose wp[10000][128] -> wpT[128][10000]
__global__ void k_prep_wp(const float* __restrict__ wp) {
    __shared__ float t[32][33];
    int vt = blockIdx.x * 32, kt = blockIdx.y * 32;
    int tx = threadIdx.x & 31, ty = threadIdx.x >> 5;   // 32 x 8
    #pragma unroll
    for (int i = 0; i < 4; i++) {
        int v = vt + ty + i * 8;
        if (v < Vn) t[ty + i * 8][tx] = wp[(size_t)v * 128 + kt + tx];
    }
    __syncthreads();
    int v = vt + tx;
    if (v < Vn) {
        #pragma unroll
        for (int i = 0; i < 4; i++) {
            int k = kt + ty + i * 8;
            g_wpT[(size_t)k * Vn + v] = t[tx][ty + i * 8];
        }
    }
}

__global__ void k_init() {
    int i = blockIdx.x * blockDim.x + threadIdx.x;
    if (i < Bn * H1n) { g_h1[0][i] = 0.f; g_h1[1][i] = 0.f; g_c1[i] = 0.f; }
    if (i < Bn * H2n) { g_h2[0][i] = 0.f; g_h2[1][i] = 0.f; g_c2[i] = 0.f; }
    if (i < Bn * 128) g_x[i] = 0.f;
    if (i < Bn) g_amax[i] = (ull)(~(unsigned int)SOS_);
}

// ---------------- k_lstm1: grid (8 rowtiles, 16 btiles), 256 thr ------------
// block: 64 rows' (16 hdims) x 16 b, k=320; double-buffered dup'd weights.
#define L1_SWD   0                                 // [2][32][64] ull = 32768
#define L1_SX    32768                             // [320][18] f   = 23040
#define L1_SG    (32768 + 23040)                   // [64][18] f    = 4608
#define L1_TOK   (L1_SG + 4608)
#define L1_SMEM  (L1_TOK + 64)

__global__ void __launch_bounds__(256) k_lstm1(const float* __restrict__ emb, int p) {
    extern __shared__ __align__(16) char sm[];
    ull   (*s_wd)[32][64] = (ull(*)[32][64])(sm + L1_SWD);
    float (*s_x)[18]      = (float(*)[18])(sm + L1_SX);
    float (*s_g)[18]      = (float(*)[18])(sm + L1_SG);
    int*  s_tok           = (int*)(sm + L1_TOK);

    const int tid = threadIdx.x;
    const int rt = blockIdx.x, bt = blockIdx.y;
    const int r0 = rt * 64, b0 = bt * 16;
    const float* __restrict__ h1old = g_h1[p];
    float* __restrict__ h1new = g_h1[p ^ 1];

    if (tid < 16) {
        ull a = g_amax[b0 + tid];
        s_tok[tid] = (int)(~(unsigned int)(a & 0xFFFFFFFFull));
    }
    __syncthreads();

    // x fill: 320 k x 16 b
    for (int idx = tid; idx < 320 * 16; idx += 256) {
        int k = idx >> 4, b = idx & 15;
        float v;
        if (k < 128) {
            int t = s_tok[b];
            v = (t == EOS_) ? 0.f : emb[(size_t)t * En + k];
        } else if (k < 192) {
            v = g_x[(b0 + b) * 128 + 64 + (k - 128)];
        } else {
            v = h1old[(b0 + b) * H1n + (k - 192)];
        }
        s_x[k][b] = v;
    }

    // prefetch + stage chunk 0 weights (32 k x 64 rows, dup'd)
    float4 pw0, pw1;
    {
        int i0 = tid, i1 = tid + 256;
        pw0 = *(const float4*)&g_w1R[(size_t)(i0 >> 4) * 512 + r0 + (i0 & 15) * 4];
        pw1 = *(const float4*)&g_w1R[(size_t)(i1 >> 4) * 512 + r0 + (i1 & 15) * 4];
    }
    {
        int i0 = tid, i1 = tid + 256;
        *(ulonglong2*)&s_wd[0][i0 >> 4][(i0 & 15) * 4]     = make_ulonglong2(dup2(pw0.x), dup2(pw0.y));
        *(ulonglong2*)&s_wd[0][i0 >> 4][(i0 & 15) * 4 + 2] = make_ulonglong2(dup2(pw0.z), dup2(pw0.w));
        *(ulonglong2*)&s_wd[0][i1 >> 4][(i1 & 15) * 4]     = make_ulonglong2(dup2(pw1.x), dup2(pw1.y));
        *(ulonglong2*)&s_wd[0][i1 >> 4][(i1 & 15) * 4 + 2] = make_ulonglong2(dup2(pw1.z), dup2(pw1.w));
    }
    __syncthreads();

    const int RP = tid >> 3, Bg = tid & 7;   // 32 row-pairs x 8 b-pairs
    ull a0 = 0, a1 = 0;

    for (int c = 0; c < 10; c++) {
        if (c < 9) {
            int kb = (c + 1) * 32;
            int i0 = tid, i1 = tid + 256;
            pw0 = *(const float4*)&g_w1R[(size_t)(kb + (i0 >> 4)) * 512 + r0 + (i0 & 15) * 4];
            pw1 = *(const float4*)&g_w1R[(size_t)(kb + (i1 >> 4)) * 512 + r0 + (i1 & 15) * 4];
        }
        #pragma unroll
        for (int kk = 0; kk < 32; kk++) {
            ulonglong2 w = *(const ulonglong2*)&s_wd[c & 1][kk][2 * RP];
            ull xp = *(const ull*)&s_x[c * 32 + kk][Bg * 2];
            fma2(a0, w.x, xp);
            fma2(a1, w.y, xp);
        }
        __syncthreads();
        if (c < 9) {
            int nb = (c + 1) & 1;
            int i0 = tid, i1 = tid + 256;
            *(ulonglong2*)&s_wd[nb][i0 >> 4][(i0 & 15) * 4]     = make_ulonglong2(dup2(pw0.x), dup2(pw0.y));
            *(ulonglong2*)&s_wd[nb][i0 >> 4][(i0 & 15) * 4 + 2] = make_ulonglong2(dup2(pw0.z), dup2(pw0.w));
            *(ulonglong2*)&s_wd[nb][i1 >> 4][(i1 & 15) * 4]     = make_ulonglong2(dup2(pw1.x), dup2(pw1.y));
            *(ulonglong2*)&s_wd[nb][i1 >> 4][(i1 & 15) * 4 + 2] = make_ulonglong2(dup2(pw1.z), dup2(pw1.w));
            __syncthreads();
        }
    }

    // gates -> smem with bias
    {
        float bl = g_b1R[r0 + 2 * RP], bh = g_b1R[r0 + 2 * RP + 1];
        float v0, v1;
        unpk2(a0, v0, v1);
        s_g[2 * RP][2 * Bg] = v0 + bl; s_g[2 * RP][2 * Bg + 1] = v1 + bl;
        unpk2(a1, v0, v1);
        s_g[2 * RP + 1][2 * Bg] = v0 + bh; s_g[2 * RP + 1][2 * Bg + 1] = v1 + bh;
    }
    __syncthreads();

    // cell update: 16 hdims x 16 b
    {
        int b = tid & 15, hl = tid >> 4;
        float gi = s_g[4 * hl][b],     gf = s_g[4 * hl + 1][b];
        float gg = s_g[4 * hl + 2][b], go = s_g[4 * hl + 3][b];
        int gidx = (b0 + b) * H1n + rt * 16 + hl;
        float c = sigm(gf) * g_c1[gidx] + sigm(gi) * tanhf(gg);
        g_c1[gidx] = c;
        h1new[gidx] = sigm(go) * tanhf(c);
    }
}

// ---------------- k_lstm2: grid (4 rowtiles, 16 btiles), 256 thr ------------
#define L2_SWD   0                                 // 32768
#define L2_SX    32768                             // [192][18] f = 13824
#define L2_SG    (32768 + 13824)                   // [64][18] f  = 4608
#define L2_SMEM  (L2_SG + 4608)

__global__ void __launch_bounds__(256) k_lstm2(int p) {
    extern __shared__ __align__(16) char sm[];
    ull   (*s_wd)[32][64] = (ull(*)[32][64])(sm + L2_SWD);
    float (*s_x)[18]      = (float(*)[18])(sm + L2_SX);
    float (*s_g)[18]      = (float(*)[18])(sm + L2_SG);

    const int tid = threadIdx.x;
    const int rt = blockIdx.x, bt = blockIdx.y;
    const int r0 = rt * 64, b0 = bt * 16;
    const float* __restrict__ h1new = g_h1[p ^ 1];
    const float* __restrict__ h2old = g_h2[p];
    float* __restrict__ h2new = g_h2[p ^ 1];

    for (int idx = tid; idx < 192 * 16; idx += 256) {
        int k = idx >> 4, b = idx & 15;
        float v = (k < 128) ? h1new[(b0 + b) * H1n + k]
                            : h2old[(b0 + b) * H2n + (k - 128)];
        s_x[k][b] = v;
    }

    float4 pw0, pw1;
    {
        int i0 = tid, i1 = tid + 256;
        pw0 = *(const float4*)&g_w2R[(size_t)(i0 >> 4) * 256 + r0 + (i0 & 15) * 4];
        pw1 = *(const float4*)&g_w2R[(size_t)(i1 >> 4) * 256 + r0 + (i1 & 15) * 4];
    }
    {
        int i0 = tid, i1 = tid + 256;
        *(ulonglong2*)&s_wd[0][i0 >> 4][(i0 & 15) * 4]     = make_ulonglong2(dup2(pw0.x), dup2(pw0.y));
        *(ulonglong2*)&s_wd[0][i0 >> 4][(i0 & 15) * 4 + 2] = make_ulonglong2(dup2(pw0.z), dup2(pw0.w));
        *(ulonglong2*)&s_wd[0][i1 >> 4][(i1 & 15) * 4]     = make_ulonglong2(dup2(pw1.x), dup2(pw1.y));
        *(ulonglong2*)&s_wd[0][i1 >> 4][(i1 & 15) * 4 + 2] = make_ulonglong2(dup2(pw1.z), dup2(pw1.w));
    }
    __syncthreads();

    const int RP = tid >> 3, Bg = tid & 7;
    ull a0 = 0, a1 = 0;

    for (int c = 0; c < 6; c++) {
        if (c < 5) {
            int kb = (c + 1) * 32;
            int i0 = tid, i1 = tid + 256;
            pw0 = *(const float4*)&g_w2R[(size_t)(kb + (i0 >> 4)) * 256 + r0 + (i0 & 15) * 4];
            pw1 = *(const float4*)&g_w2R[(size_t)(kb + (i1 >> 4)) * 256 + r0 + (i1 & 15) * 4];
        }
        #pragma unroll
        for (int kk = 0; kk < 32; kk++) {
            ulonglong2 w = *(const ulonglong2*)&s_wd[c & 1][kk][2 * RP];
            ull xp = *(const ull*)&s_x[c * 32 + kk][Bg * 2];
            fma2(a0, w.x, xp);
            fma2(a1, w.y, xp);
        }
        __syncthreads();
        if (c < 5) {
            int nb = (c + 1) & 1;
            int i0 = tid, i1 = tid + 256;
            *(ulonglong2*)&s_wd[nb][i0 >> 4][(i0 & 15) * 4]     = make_ulonglong2(dup2(pw0.x), dup2(pw0.y));
            *(ulonglong2*)&s_wd[nb][i0 >> 4][(i0 & 15) * 4 + 2] = make_ulonglong2(dup2(pw0.z), dup2(pw0.w));
            *(ulonglong2*)&s_wd[nb][i1 >> 4][(i1 & 15) * 4]     = make_ulonglong2(dup2(pw1.x), dup2(pw1.y));
            *(ulonglong2*)&s_wd[nb][i1 >> 4][(i1 & 15) * 4 + 2] = make_ulonglong2(dup2(pw1.z), dup2(pw1.w));
            __syncthreads();
        }
    }

    {
        float bl = g_b2R[r0 + 2 * RP], bh = g_b2R[r0 + 2 * RP + 1];
        float v0, v1;
        unpk2(a0, v0, v1);
        s_g[2 * RP][2 * Bg] = v0 + bl; s_g[2 * RP][2 * Bg + 1] = v1 + bl;
        unpk2(a1, v0, v1);
        s_g[2 * RP + 1][2 * Bg] = v0 + bh; s_g[2 * RP + 1][2 * Bg + 1] = v1 + bh;
    }
    __syncthreads();

    {
        int b = tid & 15, hl = tid >> 4;
        float gi = s_g[4 * hl][b],     gf = s_g[4 * hl + 1][b];
        float gg = s_g[4 * hl + 2][b], go = s_g[4 * hl + 3][b];
        int gidx = (b0 + b) * H2n + rt * 16 + hl;
        float c = sigm(gf) * g_c2[gidx] + sigm(gi) * tanhf(gg);
        g_c2[gidx] = c;
        float h = sigm(go) * tanhf(c);
        h2new[gidx] = h;
        g_x[(b0 + b) * 128 + rt * 16 + hl] = h;
    }
}

// ---------------- attention: query + energy + masked softmax + context ------
// grid 256 (one block per b), 256 threads. Also resets g_amax[b].
__global__ void __launch_bounds__(256) k_attn(
    const float* __restrict__ enc_key, const float* __restrict__ enc_val,
    const int* __restrict__ mask, const float* __restrict__ bq)
{
    __shared__ __align__(16) float s_q[64];
    __shared__ float s_h2[64];
    __shared__ float s_qp[4][64];
    __shared__ float s_e[512];
    __shared__ float s_w[512];
    __shared__ float s_red[40];
    __shared__ float s_p[4][64];
    const int b = blockIdx.x, tid = threadIdx.x;
    const int lane = tid & 31, warp = tid >> 5;

    if (tid == 0) g_amax[b] = 0ull;
    if (tid < 64) s_h2[tid] = g_x[b * 128 + tid];
    __syncthreads();

    // query = h2 @ wqT + bq
    {
        int d = tid & 63, kq = tid >> 6;
        float a = 0.f;
        #pragma unroll
        for (int k = kq * 16; k < kq * 16 + 16; k++)
            a += g_wqT[k * 64 + d] * s_h2[k];
        s_qp[kq][d] = a;
    }
    __syncthreads();
    if (tid < 64)
        s_q[tid] = s_qp[0][tid] + s_qp[1][tid] + s_qp[2][tid] + s_qp[3][tid] + bq[tid];
    __syncthreads();

    // energy: thread = (slot, d-quarter); 8 t per thread, 4 LDG.128 per t
    {
        const int slot = tid >> 2, dq = tid & 3;
        const float4* qp = (const float4*)(s_q + dq * 16);
        float4 q0 = qp[0], q1 = qp[1], q2 = qp[2], q3 = qp[3];
        #pragma unroll 4
        for (int i = 0; i < 8; i++) {
            int t = slot + 64 * i;
            const float4* kp = (const float4*)(enc_key + ((size_t)t * Bn + b) * Dn + dq * 16);
            float4 a = kp[0], c = kp[1], d = kp[2], e = kp[3];
            float pp = a.x * q0.x + a.y * q0.y + a.z * q0.z + a.w * q0.w
                     + c.x * q1.x + c.y * q1.y + c.z * q1.z + c.w * q1.w
                     + d.x * q2.x + d.y * q2.y + d.z * q2.z + d.w * q2.w
                     + e.x * q3.x + e.y * q3.y + e.z * q3.z + e.w * q3.w;
            pp += __shfl_xor_sync(0xffffffffu, pp, 1);
            pp += __shfl_xor_sync(0xffffffffu, pp, 2);
            if (dq == 0) s_e[t] = pp;
        }
    }
    __syncthreads();

    float e0 = s_e[tid], e1 = s_e[tid + 256];
    float mx = fmaxf(e0, e1);
    #pragma unroll
    for (int o = 16; o; o >>= 1) mx = fmaxf(mx, __shfl_xor_sync(0xffffffffu, mx, o));
    if (lane == 0) s_red[warp] = mx;
    __syncthreads();
    if (tid == 0) {
        float m = s_red[0];
        #pragma unroll
        for (int i = 1; i < 8; i++) m = fmaxf(m, s_red[i]);
        s_red[32] = m;
    }
    __syncthreads();
    mx = s_red[32];
    int m0 = mask[(size_t)b * Tn + tid], m1 = mask[(size_t)b * Tn + tid + 256];
    float x0 = expf(e0 - mx), x1 = expf(e1 - mx);
    float s = x0 + x1, ws = (m0 ? x0 : 0.f) + (m1 ? x1 : 0.f);
    #pragma unroll
    for (int o = 16; o; o >>= 1) {
        s  += __shfl_xor_sync(0xffffffffu, s,  o);
        ws += __shfl_xor_sync(0xffffffffu, ws, o);
    }
    if (lane == 0) { s_red[warp] = s; s_red[8 + warp] = ws; }
    __syncthreads();
    if (tid == 0) {
        float S = 0.f, W = 0.f;
        #pragma unroll
        for (int i = 0; i < 8; i++) { S += s_red[i]; W += s_red[8 + i]; }
        s_red[33] = 1.0f / (S * fmaxf(W / S, 2e-30f));
    }
    __syncthreads();
    float inv = s_red[33];
    s_w[tid]       = m0 ? x0 * inv : 0.f;
    s_w[tid + 256] = m1 ? x1 * inv : 0.f;
    __syncthreads();

    {
        int d = tid & 63, ch = tid >> 6;
        const float* vb = enc_val + (size_t)b * Dn + d;
        float a0 = 0.f, a1 = 0.f;
        #pragma unroll 4
        for (int t = ch * 128; t < ch * 128 + 128; t += 2) {
            a0 += s_w[t]     * vb[(size_t)t * (Bn * Dn)];
            a1 += s_w[t + 1] * vb[(size_t)(t + 1) * (Bn * Dn)];
        }
        s_p[ch][d] = a0 + a1;
    }
    __syncthreads();
    if (tid < 64) {
        float c = s_p[0][tid] + s_p[1][tid] + s_p[2][tid] + s_p[3][tid];
        g_x[b * 128 + 64 + tid] = c;
    }
}

// ---------------- pred GEMM (double-buffered staging) + fused argmax --------
__global__ void __launch_bounds__(256) k_pred(const float* __restrict__ bp,
                                              float* __restrict__ out, int step) {
    __shared__ __align__(16) ull   s_xd[32][128];     // 32 KB
    __shared__ __align__(16) float s_wt[2][16][128];  // 16 KB
    const int tid = threadIdx.x;
    const int b0 = blockIdx.y * 32;
    const int vt = blockIdx.x;

    for (int idx = tid; idx < 32 * 128; idx += 256) {
        int b = idx >> 7, k = idx & 127;
        s_xd[b][k] = dup2(g_x[(b0 + b) * 128 + k]);
    }

    const int vq = tid & 31, bq = tid >> 5;
    const int v0 = vt * 128 + vq * 4;
    const bool vok = (v0 + 3) < Vn;

    // stage chunk 0
    {
        #pragma unroll
        for (int i = 0; i < 2; i++) {
            int idx = tid + i * 256;
            int kr = idx >> 5, j4 = idx & 31;
            int v = vt * 128 + j4 * 4;
            float4 val = make_float4(0.f, 0.f, 0.f, 0.f);
            if (v + 3 < Vn)
                val = *(const float4*)&g_wpT[(size_t)kr * Vn + v];
            *(float4*)&s_wt[0][kr][j4 * 4] = val;
        }
    }
    __syncthreads();

    ull acc0[4] = {}, acc1[4] = {};
    float4 pv0, pv1;
    #pragma unroll 1
    for (int kc = 0; kc < 8; kc++) {
        if (kc < 7) {
            int idx0 = tid, idx1 = tid + 256;
            int kr0 = idx0 >> 5, j40 = idx0 & 31;
            int kr1 = idx1 >> 5, j41 = idx1 & 31;
            int va = vt * 128 + j40 * 4, vb = vt * 128 + j41 * 4;
            pv0 = make_float4(0.f, 0.f, 0.f, 0.f);
            pv1 = make_float4(0.f, 0.f, 0.f, 0.f);
            if (va + 3 < Vn) pv0 = *(const float4*)&g_wpT[(size_t)((kc + 1) * 16 + kr0) * Vn + va];
            if (vb + 3 < Vn) pv1 = *(const float4*)&g_wpT[(size_t)((kc + 1) * 16 + kr1) * Vn + vb];
        }
        #pragma unroll
        for (int kr = 0; kr < 16; kr++) {
            int k = kc * 16 + kr;
            ulonglong2 w = *(const ulonglong2*)&s_wt[kc & 1][kr][vq * 4];
            #pragma unroll
            for (int b = 0; b < 4; b++) {
                ull xd = s_xd[bq * 4 + b][k];
                fma2(acc0[b], w.x, xd);
                fma2(acc1[b], w.y, xd);
            }
        }
        if (kc < 7) {
            int nb = (kc + 1) & 1;
            int idx0 = tid, idx1 = tid + 256;
            *(float4*)&s_wt[nb][idx0 >> 5][(idx0 & 31) * 4] = pv0;
            *(float4*)&s_wt[nb][idx1 >> 5][(idx1 & 31) * 4] = pv1;
            __syncthreads();
        }
    }

    float bs0 = 0.f, bs1 = 0.f, bs2 = 0.f, bs3 = 0.f;
    if (vok) {
        float4 b4 = *(const float4*)&bp[v0];
        bs0 = b4.x; bs1 = b4.y; bs2 = b4.z; bs3 = b4.w;
    }

    #pragma unroll
    for (int b = 0; b < 4; b++) {
        int bi = b0 + bq * 4 + b;
        float r0, r1, r2, r3;
        unpk2(acc0[b], r0, r1);
        unpk2(acc1[b], r2, r3);
        r0 += bs0; r1 += bs1; r2 += bs2; r3 += bs3;
        if (vok) {
            __stcs((float4*)(out + (size_t)bi * (ML * Vn) + (size_t)step * Vn + v0),
                   make_float4(r0, r1, r2, r3));
        }
        float best = r0; int bv = v0;
        if (r1 > best) { best = r1; bv = v0 + 1; }
        if (r2 > best) { best = r2; bv = v0 + 2; }
        if (r3 > best) { best = r3; bv = v0 + 3; }
        ull pk = vok ? (((ull)fkey(best) << 32) | (unsigned int)(~bv)) : 0ull;
        #pragma unroll
        for (int o = 16; o; o >>= 1) {
            ull other = __shfl_down_sync(0xffffffffu, pk, o);
            if (other > pk) pk = other;
        }
        if (vq == 0) atomicMax(&g_amax[bi], pk);
    }
}

// ---------------- host ------------------------------------------------------
extern "C" void kernel_launch(void* const* d_in, const int* in_sizes, int n_in,
                              void* d_out, int out_size) {
    const float* enc_key = (const float*)d_in[0];
    const float* enc_val = (const float*)d_in[1];
    const int*   mask    = (const int*)d_in[2];
    const float* emb     = (const float*)d_in[3];
    const float* w_ih1   = (const float*)d_in[4];
    const float* w_hh1   = (const float*)d_in[5];
    const float* b_ih1   = (const float*)d_in[6];
    const float* b_hh1   = (const float*)d_in[7];
    const float* w_ih2   = (const float*)d_in[8];
    const float* w_hh2   = (const float*)d_in[9];
    const float* b_ih2   = (const float*)d_in[10];
    const float* b_hh2   = (const float*)d_in[11];
    const float* wq      = (const float*)d_in[12];
    const float* bq      = (const float*)d_in[13];
    const float* wp      = (const float*)d_in[14];
    const float* bp      = (const float*)d_in[15];
    float* out = (float*)d_out;

    static int s_attr_done = 0;
    if (!s_attr_done) {
        cudaFuncSetAttribute(k_lstm1, cudaFuncAttributeMaxDynamicSharedMemorySize, L1_SMEM);
        cudaFuncSetAttribute(k_lstm2, cudaFuncAttributeMaxDynamicSharedMemorySize, L2_SMEM);
        s_attr_done = 1;
    }

    k_prep_small<<<640, 256>>>(w_ih1, w_hh1, b_ih1, b_hh1,
                               w_ih2, w_hh2, b_ih2, b_hh2, wq);
    k_prep_wp<<<dim3(313, 4), 256>>>(wp);
    k_init<<<128, 256>>>();
    for (int s = 0; s < ML; s++) {
        int p = s & 1;
        k_lstm1<<<dim3(8, 16), 256, L1_SMEM>>>(emb, p);
        k_lstm2<<<dim3(4, 16), 256, L2_SMEM>>>(p);
        k_attn<<<256, 256>>>(enc_key, enc_val, mask, bq);
        k_pred<<<dim3(79, 8), 256>>>(bp, out, s);
    }
}